// round 5
// baseline (speedup 1.0000x reference)
#include <cuda_runtime.h>
#include <cuda_bf16.h>
#include <stdint.h>

// ---------------- Problem constants (fixed dataset) ----------------
#define NMAX 100000
#define EMAX 1600000
#define DIM_IN  512
#define DIM_HID 128
#define DIM_OUT 64

#define W0_ELEMS (DIM_HID * DIM_IN)    // 65536
#define W1_ELEMS (DIM_HID * DIM_HID)   // 16384
#define W2_ELEMS (DIM_OUT * DIM_HID)   // 8192
#define W_TOTAL  (W0_ELEMS + W1_ELEMS + W2_ELEMS)

// ---------------- Device scratch (no allocations allowed) ----------------
__device__ float g_bufA[(size_t)NMAX * DIM_HID];   // gemm outputs (fp32)
__device__ uint32_t g_bufB[(size_t)NMAX * DIM_HID]; // spmm outputs (packed hi|lo bf16)
__device__ int   g_deg[NMAX];
__device__ int   g_cnt[NMAX];
__device__ int   g_rowptr[NMAX + 1];
__device__ int2  g_epack[EMAX];                    // (col, val bits) per CSR slot
__device__ __nv_bfloat16 g_Whi[W_TOTAL];
__device__ __nv_bfloat16 g_Wlo[W_TOTAL];

// ---------------- helpers ----------------
__device__ __forceinline__ uint32_t smem_u32(const void* p) {
    uint32_t a;
    asm("{ .reg .u64 t; cvta.to.shared.u64 t, %1; cvt.u32.u64 %0, t; }" : "=r"(a) : "l"(p));
    return a;
}
__device__ __forceinline__ uint32_t sw128(uint32_t b) { return b ^ ((b >> 3) & 0x70); }

__device__ __forceinline__ void ldsm_x4(uint32_t* r, uint32_t addr) {
    asm volatile("ldmatrix.sync.aligned.m8n8.x4.shared.b16 {%0,%1,%2,%3}, [%4];"
                 : "=r"(r[0]), "=r"(r[1]), "=r"(r[2]), "=r"(r[3]) : "r"(addr));
}
__device__ __forceinline__ void mma16816(float* d, const uint32_t* a, const uint32_t* b) {
    asm volatile(
        "mma.sync.aligned.m16n8k16.row.col.f32.bf16.bf16.f32 "
        "{%0,%1,%2,%3}, {%4,%5,%6,%7}, {%8,%9}, {%0,%1,%2,%3};"
        : "+f"(d[0]), "+f"(d[1]), "+f"(d[2]), "+f"(d[3])
        : "r"(a[0]), "r"(a[1]), "r"(a[2]), "r"(a[3]), "r"(b[0]), "r"(b[1]));
}

// fp32 -> (hi, lo) bf16 pairs, 4 floats at a time
__device__ __forceinline__ void cvt_hilo(float4 v, uint2& hi, uint2& lo) {
    __nv_bfloat162 h01 = __floats2bfloat162_rn(v.x, v.y);
    __nv_bfloat162 h23 = __floats2bfloat162_rn(v.z, v.w);
    __nv_bfloat162 l01 = __floats2bfloat162_rn(v.x - __bfloat162float(h01.x),
                                               v.y - __bfloat162float(h01.y));
    __nv_bfloat162 l23 = __floats2bfloat162_rn(v.z - __bfloat162float(h23.x),
                                               v.w - __bfloat162float(h23.y));
    hi = make_uint2(*(uint32_t*)&h01, *(uint32_t*)&h23);
    lo = make_uint2(*(uint32_t*)&l01, *(uint32_t*)&l23);
}

// fp32 -> packed u32: (bf16 hi << 16) | bf16 lo
__device__ __forceinline__ uint32_t pack_hilo(float v) {
    __nv_bfloat16 bh = __float2bfloat16(v);
    __nv_bfloat16 bl = __float2bfloat16(v - __bfloat162float(bh));
    return ((uint32_t)__bfloat16_as_ushort(bh) << 16) | (uint32_t)__bfloat16_as_ushort(bl);
}

// ---------------- W pre-split (once per launch, ~2us) ----------------
__global__ void convert_w_kernel(const float* __restrict__ W0,
                                 const float* __restrict__ W1,
                                 const float* __restrict__ W2) {
    int i = blockIdx.x * blockDim.x + threadIdx.x;
    if (i >= W_TOTAL) return;
    float v;
    if (i < W0_ELEMS)                 v = W0[i];
    else if (i < W0_ELEMS + W1_ELEMS) v = W1[i - W0_ELEMS];
    else                              v = W2[i - W0_ELEMS - W1_ELEMS];
    __nv_bfloat16 bh = __float2bfloat16(v);
    __nv_bfloat16 bl = __float2bfloat16(v - __bfloat162float(bh));
    g_Whi[i] = bh;
    g_Wlo[i] = bl;
}

// ---------------- CSR build ----------------
__global__ void zero_counts_kernel(int n) {
    int i = blockIdx.x * blockDim.x + threadIdx.x;
    if (i < n) { g_deg[i] = 0; g_cnt[i] = 0; }
}

__global__ void hist_kernel(const int* __restrict__ rows, int E) {
    int i = blockIdx.x * blockDim.x + threadIdx.x;
    if (i < E) atomicAdd(&g_deg[rows[i]], 1);
}

// Single-block exclusive scan over g_deg -> g_rowptr. blockDim must be 1024.
__global__ void scan_kernel(int n) {
    __shared__ int warpsums[32];
    __shared__ int s_carry;
    int tid = threadIdx.x, lane = tid & 31, wid = tid >> 5;
    if (tid == 0) s_carry = 0;
    __syncthreads();
    for (int base = 0; base < n; base += 1024) {
        int i = base + tid;
        int v = (i < n) ? g_deg[i] : 0;
        int x = v;
        #pragma unroll
        for (int o = 1; o < 32; o <<= 1) {
            int y = __shfl_up_sync(0xffffffffu, x, o);
            if (lane >= o) x += y;
        }
        if (lane == 31) warpsums[wid] = x;
        __syncthreads();
        if (wid == 0) {
            int s = warpsums[lane];
            #pragma unroll
            for (int o = 1; o < 32; o <<= 1) {
                int y = __shfl_up_sync(0xffffffffu, s, o);
                if (lane >= o) s += y;
            }
            warpsums[lane] = s;
        }
        __syncthreads();
        int pref = (wid > 0) ? warpsums[wid - 1] : 0;
        int carry = s_carry;
        int incl = x + pref + carry;
        if (i < n) g_rowptr[i] = incl - v;   // exclusive prefix
        __syncthreads();
        if (tid == 1023) s_carry = incl;
        __syncthreads();
    }
    if (tid == 0) g_rowptr[n] = s_carry;
}

__global__ void scatter_kernel(const int* __restrict__ rows,
                               const int* __restrict__ cols,
                               const float* __restrict__ vals, int E) {
    int i = blockIdx.x * blockDim.x + threadIdx.x;
    if (i < E) {
        int r = rows[i];
        int p = g_rowptr[r] + atomicAdd(&g_cnt[r], 1);
        g_epack[p] = make_int2(cols[i], __float_as_int(vals[i]));
    }
}

// ---------------- Tensor-core GEMM via mma.sync ----------------
// C[M,BN] = A[M,K] * W[BN,K]^T, fp32 emulated by bf16 hi/lo split:
//   D += Ahi*Bhi + Ahi*Blo + Alo*Bhi   (error ~2^-16)
// smem rows = 128 bytes: [hi 32xbf16 | lo 32xbf16], SW128 swizzle, dbl-buffered.
// APACK=false: A is fp32, converted in-kernel.
// APACK=true:  A is packed u32 (bf16hi<<16|bf16lo), unpacked via PRMT.
// W is pre-split into g_Whi/g_Wlo planes (straight 16B copies into smem).
template <int BM, int BN, int WM, int WN, int K, bool APACK>
__global__ void __launch_bounds__(WM * WN * 32, 1)
mma_gemm_kernel(const void* __restrict__ Av,
                const __nv_bfloat16* __restrict__ Whi,
                const __nv_bfloat16* __restrict__ Wlo,
                float* __restrict__ C, int M)
{
    constexpr int THREADS = WM * WN * 32;
    constexpr int NCHUNK  = K / 32;
    constexpr int ASZ = BM * 128;             // bytes per A buffer
    constexpr int BSZ = BN * 128;             // bytes per B buffer
    constexpr int AL  = BM * 8 / THREADS;     // 16B loads per thread (A)
    constexpr int BU  = BN * 4 / THREADS;     // 16B units per thread (per W plane)
    constexpr int MT  = BM / WM / 16;         // m16 tiles per warp
    constexpr int NT  = BN / WN / 8;          // n8  tiles per warp

    extern __shared__ __align__(1024) char smem[];
    const uint32_t sb = smem_u32(smem);

    const int tid = threadIdx.x;
    const int l   = tid & 31;
    const int w   = tid >> 5;
    const int wmBase = (w % WM) * (BM / WM);
    const int wnBase = (w / WM) * (BN / WN);
    const int m0 = blockIdx.x * BM;

    const float*    Af = (const float*)Av;
    const uint32_t* Ap = (const uint32_t*)Av;

    float acc[MT][NT][4];
    #pragma unroll
    for (int i = 0; i < MT; i++)
        #pragma unroll
        for (int j = 0; j < NT; j++)
            #pragma unroll
            for (int q = 0; q < 4; q++) acc[i][j][q] = 0.f;

    float4 regA[APACK ? 1 : AL];
    uint4  regAp[APACK ? AL : 1];
    uint4  regBh[BU], regBl[BU];

    // lane-derived ldmatrix addressing components
    const int arow = l & 15;
    const int acol = (l & 16) ? 16 : 0;
    const int brow = ((l & 16) ? 8 : 0) + (l & 7);
    const int bcol = (l & 8) ? 16 : 0;

    auto loadChunk = [&](int c) {
        const int k0 = c * 32;
        #pragma unroll
        for (int i = 0; i < AL; i++) {
            int idx = tid + i * THREADS;
            int r = idx >> 3, c4 = (idx & 7) << 2;
            int row = m0 + r; if (row >= M) row = M - 1;
            if constexpr (APACK)
                regAp[i] = __ldg((const uint4*)(Ap + (size_t)row * K + k0 + c4));
            else
                regA[i] = __ldg((const float4*)(Af + (size_t)row * K + k0 + c4));
        }
        #pragma unroll
        for (int i = 0; i < BU; i++) {
            int idx = tid + i * THREADS;
            int r = idx >> 2, u = idx & 3;
            size_t off = (size_t)r * K + k0 + u * 8;
            regBh[i] = __ldg((const uint4*)(Whi + off));
            regBl[i] = __ldg((const uint4*)(Wlo + off));
        }
    };

    auto stsChunk = [&](int b) {
        char* abase = smem + b * (ASZ + BSZ);
        char* bbase = abase + ASZ;
        #pragma unroll
        for (int i = 0; i < AL; i++) {
            int idx = tid + i * THREADS;
            int r = idx >> 3, c4 = (idx & 7) << 2;
            if constexpr (APACK) {
                uint4 p = regAp[i];
                uint32_t h0 = __byte_perm(p.x, p.y, 0x7632);
                uint32_t h1 = __byte_perm(p.z, p.w, 0x7632);
                uint32_t l0 = __byte_perm(p.x, p.y, 0x5410);
                uint32_t l1 = __byte_perm(p.z, p.w, 0x5410);
                *(uint2*)(abase + sw128((uint32_t)(r * 128 + c4 * 2)))      = make_uint2(h0, h1);
                *(uint2*)(abase + sw128((uint32_t)(r * 128 + 64 + c4 * 2))) = make_uint2(l0, l1);
            } else {
                uint2 hi, lo; cvt_hilo(regA[i], hi, lo);
                *(uint2*)(abase + sw128((uint32_t)(r * 128 + c4 * 2)))      = hi;
                *(uint2*)(abase + sw128((uint32_t)(r * 128 + 64 + c4 * 2))) = lo;
            }
        }
        #pragma unroll
        for (int i = 0; i < BU; i++) {
            int idx = tid + i * THREADS;
            int r = idx >> 2, u = idx & 3;
            *(uint4*)(bbase + sw128((uint32_t)(r * 128 + u * 16)))      = regBh[i];
            *(uint4*)(bbase + sw128((uint32_t)(r * 128 + 64 + u * 16))) = regBl[i];
        }
    };

    auto compute = [&](int b) {
        const uint32_t sA = sb + b * (ASZ + BSZ);
        const uint32_t sB = sA + ASZ;
        #pragma unroll
        for (int kg = 0; kg < 2; kg++) {
            const int kb = kg * 32;
            uint32_t aH[MT][4], aLo[MT][4];
            #pragma unroll
            for (int mt = 0; mt < MT; mt++) {
                uint32_t rowb = (uint32_t)((wmBase + mt * 16 + arow) * 128);
                ldsm_x4(aH[mt],  sA + sw128(rowb + kb + acol));
                ldsm_x4(aLo[mt], sA + sw128(rowb + 64 + kb + acol));
            }
            uint32_t bH[NT][2], bLo[NT][2];
            #pragma unroll
            for (int nt = 0; nt < NT; nt += 2) {
                uint32_t rowb = (uint32_t)((wnBase + nt * 8 + brow) * 128);
                uint32_t t[4];
                ldsm_x4(t, sB + sw128(rowb + kb + bcol));
                bH[nt][0] = t[0]; bH[nt][1] = t[1];
                bH[nt + 1][0] = t[2]; bH[nt + 1][1] = t[3];
                ldsm_x4(t, sB + sw128(rowb + 64 + kb + bcol));
                bLo[nt][0] = t[0]; bLo[nt][1] = t[1];
                bLo[nt + 1][0] = t[2]; bLo[nt + 1][1] = t[3];
            }
            #pragma unroll
            for (int mt = 0; mt < MT; mt++)
                #pragma unroll
                for (int nt = 0; nt < NT; nt++) {
                    mma16816(acc[mt][nt], aH[mt],  bH[nt]);
                    mma16816(acc[mt][nt], aH[mt],  bLo[nt]);
                    mma16816(acc[mt][nt], aLo[mt], bH[nt]);
                }
        }
    };

    // prologue
    loadChunk(0);
    stsChunk(0);
    __syncthreads();

    for (int c = 0; c < NCHUNK; c++) {
        if (c + 1 < NCHUNK) loadChunk(c + 1);
        compute(c & 1);
        if (c + 1 < NCHUNK) {
            __syncthreads();
            stsChunk((c + 1) & 1);
            __syncthreads();
        }
    }

    // epilogue: write fp32 accumulators
    #pragma unroll
    for (int mt = 0; mt < MT; mt++) {
        int m = m0 + wmBase + mt * 16 + (l >> 2);
        #pragma unroll
        for (int nt = 0; nt < NT; nt++) {
            int nn = wnBase + nt * 8 + ((l & 3) << 1);
            if (m < M)
                *(float2*)(C + (size_t)m * BN + nn) =
                    make_float2(acc[mt][nt][0], acc[mt][nt][1]);
            if (m + 8 < M)
                *(float2*)(C + (size_t)(m + 8) * BN + nn) =
                    make_float2(acc[mt][nt][2], acc[mt][nt][3]);
        }
    }
}

// ---------------- SpMM (CSR, warp per row, packed edges, 2x unroll) --------
// PACKOUT: write packed (bf16hi<<16|bf16lo) u32 instead of fp32 (feeds GEMM).
template <int WIDTH, bool RELU, bool PACKOUT>
__global__ void spmm_kernel(const float* __restrict__ h,
                            void* __restrict__ outv, int n) {
    int warp = (blockIdx.x * blockDim.x + threadIdx.x) >> 5;
    int lane = threadIdx.x & 31;
    if (warp >= n) return;
    int s = g_rowptr[warp];
    int e = g_rowptr[warp + 1];

    if (WIDTH == 128) {
        float4 acc = make_float4(0.f, 0.f, 0.f, 0.f);
        int i = s;
        for (; i + 2 <= e; i += 2) {
            int2 p0 = g_epack[i];
            int2 p1 = g_epack[i + 1];
            float v0 = __int_as_float(p0.y);
            float v1 = __int_as_float(p1.y);
            float4 h0 = __ldg((const float4*)(h + (size_t)p0.x * 128) + lane);
            float4 h1 = __ldg((const float4*)(h + (size_t)p1.x * 128) + lane);
            acc.x += v0 * h0.x; acc.y += v0 * h0.y;
            acc.z += v0 * h0.z; acc.w += v0 * h0.w;
            acc.x += v1 * h1.x; acc.y += v1 * h1.y;
            acc.z += v1 * h1.z; acc.w += v1 * h1.w;
        }
        if (i < e) {
            int2 p = g_epack[i];
            float v = __int_as_float(p.y);
            float4 hv = __ldg((const float4*)(h + (size_t)p.x * 128) + lane);
            acc.x += v * hv.x; acc.y += v * hv.y;
            acc.z += v * hv.z; acc.w += v * hv.w;
        }
        if (RELU) {
            acc.x = fmaxf(acc.x, 0.f); acc.y = fmaxf(acc.y, 0.f);
            acc.z = fmaxf(acc.z, 0.f); acc.w = fmaxf(acc.w, 0.f);
        }
        if (PACKOUT) {
            uint4 o = make_uint4(pack_hilo(acc.x), pack_hilo(acc.y),
                                 pack_hilo(acc.z), pack_hilo(acc.w));
            ((uint4*)((uint32_t*)outv + (size_t)warp * 128))[lane] = o;
        } else {
            ((float4*)((float*)outv + (size_t)warp * 128))[lane] = acc;
        }
    } else {  // WIDTH == 64, fp32 out
        float2 acc = make_float2(0.f, 0.f);
        int i = s;
        for (; i + 2 <= e; i += 2) {
            int2 p0 = g_epack[i];
            int2 p1 = g_epack[i + 1];
            float v0 = __int_as_float(p0.y);
            float v1 = __int_as_float(p1.y);
            float2 h0 = __ldg((const float2*)(h + (size_t)p0.x * 64) + lane);
            float2 h1 = __ldg((const float2*)(h + (size_t)p1.x * 64) + lane);
            acc.x += v0 * h0.x; acc.y += v0 * h0.y;
            acc.x += v1 * h1.x; acc.y += v1 * h1.y;
        }
        if (i < e) {
            int2 p = g_epack[i];
            float v = __int_as_float(p.y);
            float2 hv = __ldg((const float2*)(h + (size_t)p.x * 64) + lane);
            acc.x += v * hv.x; acc.y += v * hv.y;
        }
        if (RELU) { acc.x = fmaxf(acc.x, 0.f); acc.y = fmaxf(acc.y, 0.f); }
        ((float2*)((float*)outv + (size_t)warp * 64))[lane] = acc;
    }
}

// ---------------- Launcher ----------------
extern "C" void kernel_launch(void* const* d_in, const int* in_sizes, int n_in,
                              void* d_out, int out_size) {
    const float* x    = (const float*)d_in[0];
    const int*   rows = (const int*)  d_in[1];
    const int*   cols = (const int*)  d_in[2];
    const float* vals = (const float*)d_in[3];
    const float* W0   = (const float*)d_in[4];
    const float* W1   = (const float*)d_in[5];
    const float* W2   = (const float*)d_in[6];
    float* out = (float*)d_out;

    int n = in_sizes[0] / DIM_IN;   // 100000
    int E = in_sizes[1];            // 1600000

    float* bufA; uint32_t* bufB;
    __nv_bfloat16 *whi, *wlo;
    cudaGetSymbolAddress((void**)&bufA, g_bufA);
    cudaGetSymbolAddress((void**)&bufB, g_bufB);
    cudaGetSymbolAddress((void**)&whi, g_Whi);
    cudaGetSymbolAddress((void**)&wlo, g_Wlo);

    const int smem0 = 2 * (128 * 128 + 128 * 128);  // 64 KB (BN=128)
    const int smem2 = 2 * (128 * 128 + 64 * 128);   // 48 KB (BN=64)
    cudaFuncSetAttribute((const void*)mma_gemm_kernel<128, 128, 2, 4, 512, false>,
                         cudaFuncAttributeMaxDynamicSharedMemorySize, smem0);
    cudaFuncSetAttribute((const void*)mma_gemm_kernel<128, 128, 2, 4, 128, true>,
                         cudaFuncAttributeMaxDynamicSharedMemorySize, smem0);
    cudaFuncSetAttribute((const void*)mma_gemm_kernel<128, 64, 4, 2, 128, true>,
                         cudaFuncAttributeMaxDynamicSharedMemorySize, smem2);

    int gemmGrid = (n + 127) / 128;
    int spmmGrid = (n + 7) / 8;     // 8 warps per 256-thread block

    // W pre-split (tiny)
    convert_w_kernel<<<(W_TOTAL + 255) / 256, 256>>>(W0, W1, W2);

    // ---- CSR build ----
    zero_counts_kernel<<<(n + 255) / 256, 256>>>(n);
    hist_kernel<<<(E + 255) / 256, 256>>>(rows, E);
    scan_kernel<<<1, 1024>>>(n);
    scatter_kernel<<<(E + 255) / 256, 256>>>(rows, cols, vals, E);

    // layer 0: x @ W0^T -> spmm -> relu (packed out)
    mma_gemm_kernel<128, 128, 2, 4, 512, false><<<gemmGrid, 256, smem0>>>(
        x, whi, wlo, bufA, n);
    spmm_kernel<128, true, true><<<spmmGrid, 256>>>(bufA, bufB, n);

    // layer 1: h @ W1^T -> spmm -> relu (packed out)
    mma_gemm_kernel<128, 128, 2, 4, 128, true><<<gemmGrid, 256, smem0>>>(
        bufB, whi + W0_ELEMS, wlo + W0_ELEMS, bufA, n);
    spmm_kernel<128, true, true><<<spmmGrid, 256>>>(bufA, bufB, n);

    // layer 2: h @ W2^T -> spmm (no relu, fp32 out)
    mma_gemm_kernel<128, 64, 4, 2, 128, true><<<gemmGrid, 256, smem2>>>(
        bufB, whi + W0_ELEMS + W1_ELEMS, wlo + W0_ELEMS + W1_ELEMS, bufA, n);
    spmm_kernel<64, false, false><<<spmmGrid, 256>>>(bufA, out, n);
}

// round 6
// speedup vs baseline: 1.1656x; 1.1656x over previous
#include <cuda_runtime.h>
#include <cuda_bf16.h>
#include <stdint.h>

// ---------------- Problem constants (fixed dataset) ----------------
#define NMAX 100000
#define EMAX 1600000
#define DIM_IN  512
#define DIM_HID 128
#define DIM_OUT 64

#define SCAN_BLK 1024
#define NBLKS ((NMAX + SCAN_BLK - 1) / SCAN_BLK)   // 98

// ---------------- Device scratch (no allocations allowed) ----------------
__device__ float g_bufA[(size_t)NMAX * DIM_HID];   // gemm outputs
__device__ float g_bufB[(size_t)NMAX * DIM_HID];   // spmm outputs
__device__ int   g_deg[NMAX];
__device__ int   g_cnt[NMAX];
__device__ int   g_rowptr[NMAX + 1];
__device__ int   g_blksum[128];
__device__ int2  g_epack[EMAX];                    // (col, val bits) per CSR slot

// ---------------- helpers ----------------
__device__ __forceinline__ uint32_t smem_u32(const void* p) {
    uint32_t a;
    asm("{ .reg .u64 t; cvta.to.shared.u64 t, %1; cvt.u32.u64 %0, t; }" : "=r"(a) : "l"(p));
    return a;
}
__device__ __forceinline__ uint32_t sw128(uint32_t b) { return b ^ ((b >> 3) & 0x70); }

__device__ __forceinline__ void ldsm_x4(uint32_t* r, uint32_t addr) {
    asm volatile("ldmatrix.sync.aligned.m8n8.x4.shared.b16 {%0,%1,%2,%3}, [%4];"
                 : "=r"(r[0]), "=r"(r[1]), "=r"(r[2]), "=r"(r[3]) : "r"(addr));
}
__device__ __forceinline__ void mma16816(float* d, const uint32_t* a, const uint32_t* b) {
    asm volatile(
        "mma.sync.aligned.m16n8k16.row.col.f32.bf16.bf16.f32 "
        "{%0,%1,%2,%3}, {%4,%5,%6,%7}, {%8,%9}, {%0,%1,%2,%3};"
        : "+f"(d[0]), "+f"(d[1]), "+f"(d[2]), "+f"(d[3])
        : "r"(a[0]), "r"(a[1]), "r"(a[2]), "r"(a[3]), "r"(b[0]), "r"(b[1]));
}

// fp32 -> (hi, lo) bf16 pairs, 4 floats at a time
__device__ __forceinline__ void cvt_hilo(float4 v, uint2& hi, uint2& lo) {
    __nv_bfloat162 h01 = __floats2bfloat162_rn(v.x, v.y);
    __nv_bfloat162 h23 = __floats2bfloat162_rn(v.z, v.w);
    __nv_bfloat162 l01 = __floats2bfloat162_rn(v.x - __bfloat162float(h01.x),
                                               v.y - __bfloat162float(h01.y));
    __nv_bfloat162 l23 = __floats2bfloat162_rn(v.z - __bfloat162float(h23.x),
                                               v.w - __bfloat162float(h23.y));
    hi = make_uint2(*(uint32_t*)&h01, *(uint32_t*)&h23);
    lo = make_uint2(*(uint32_t*)&l01, *(uint32_t*)&l23);
}

// ---------------- CSR build ----------------
__global__ void zero_counts_kernel(int n) {
    int i = blockIdx.x * blockDim.x + threadIdx.x;
    if (i < n) { g_deg[i] = 0; g_cnt[i] = 0; }
}

__global__ void hist_kernel(const int* __restrict__ rows, int E) {
    int i = blockIdx.x * blockDim.x + threadIdx.x;
    if (i < E) atomicAdd(&g_deg[rows[i]], 1);
}

// Phase A: per-block scan of 1024 degrees; local exclusive prefix + block total.
__global__ void scan_blocks_kernel(int n) {
    __shared__ int warpsums[32];
    int tid = threadIdx.x, lane = tid & 31, wid = tid >> 5;
    int i = blockIdx.x * SCAN_BLK + tid;
    int v = (i < n) ? g_deg[i] : 0;
    int x = v;
    #pragma unroll
    for (int o = 1; o < 32; o <<= 1) {
        int y = __shfl_up_sync(0xffffffffu, x, o);
        if (lane >= o) x += y;
    }
    if (lane == 31) warpsums[wid] = x;
    __syncthreads();
    if (wid == 0) {
        int s = warpsums[lane];
        #pragma unroll
        for (int o = 1; o < 32; o <<= 1) {
            int y = __shfl_up_sync(0xffffffffu, s, o);
            if (lane >= o) s += y;
        }
        warpsums[lane] = s;
    }
    __syncthreads();
    int pref = (wid > 0) ? warpsums[wid - 1] : 0;
    int incl = x + pref;
    if (i < n) g_rowptr[i] = incl - v;     // block-local exclusive prefix
    if (tid == SCAN_BLK - 1) g_blksum[blockIdx.x] = incl;
}

// Phase B: single warp-ish block scans the (<=128) block totals, exclusive.
__global__ void scan_partials_kernel(int nb, int n) {
    __shared__ int warpsums[4];
    int tid = threadIdx.x, lane = tid & 31, wid = tid >> 5;   // 128 threads
    int v = (tid < nb) ? g_blksum[tid] : 0;
    int x = v;
    #pragma unroll
    for (int o = 1; o < 32; o <<= 1) {
        int y = __shfl_up_sync(0xffffffffu, x, o);
        if (lane >= o) x += y;
    }
    if (lane == 31) warpsums[wid] = x;
    __syncthreads();
    if (tid == 0) {
        int c = 0;
        #pragma unroll
        for (int q = 0; q < 4; q++) { int t = warpsums[q]; warpsums[q] = c; c += t; }
    }
    __syncthreads();
    int incl = x + warpsums[wid];
    if (tid < nb) g_blksum[tid] = incl - v;   // exclusive block offsets
    if (tid == nb - 1) g_rowptr[n] = incl;    // grand total
}

// Phase C: add block offsets.
__global__ void scan_add_kernel(int n) {
    int i = blockIdx.x * SCAN_BLK + threadIdx.x;
    if (i < n) g_rowptr[i] += g_blksum[blockIdx.x];
}

__global__ void scatter_kernel(const int* __restrict__ rows,
                               const int* __restrict__ cols,
                               const float* __restrict__ vals, int E) {
    int i = blockIdx.x * blockDim.x + threadIdx.x;
    if (i < E) {
        int r = rows[i];
        int p = g_rowptr[r] + atomicAdd(&g_cnt[r], 1);
        g_epack[p] = make_int2(cols[i], __float_as_int(vals[i]));
    }
}

// ---------------- Tensor-core GEMM via mma.sync ----------------
// C[M,BN] = A[M,K] * W[BN,K]^T, fp32 emulated by bf16 hi/lo split:
//   D += Ahi*Bhi + Ahi*Blo + Alo*Bhi   (error ~2^-16, well under 1e-3)
// Each K-chunk = 32 fp32 -> smem rows of 128 bytes: [hi 32xbf16 | lo 32xbf16],
// SW128 swizzle (conflict-free ldmatrix). Double-buffered.
template <int BM, int BN, int WM, int WN, int K>
__global__ void __launch_bounds__(WM * WN * 32, 1)
mma_gemm_kernel(const float* __restrict__ A, const float* __restrict__ W,
                float* __restrict__ C, int M)
{
    constexpr int THREADS = WM * WN * 32;
    constexpr int NCHUNK  = K / 32;
    constexpr int ASZ = BM * 128;          // bytes per A buffer
    constexpr int BSZ = BN * 128;          // bytes per B buffer
    constexpr int AL  = BM * 8 / THREADS;  // float4 loads per thread (A)
    constexpr int BL  = BN * 8 / THREADS;  // float4 loads per thread (B)
    constexpr int MT  = BM / WM / 16;      // m16 tiles per warp
    constexpr int NT  = BN / WN / 8;       // n8  tiles per warp

    extern __shared__ __align__(1024) char smem[];
    const uint32_t sb = smem_u32(smem);

    const int tid = threadIdx.x;
    const int l   = tid & 31;
    const int w   = tid >> 5;
    const int wmBase = (w % WM) * (BM / WM);
    const int wnBase = (w / WM) * (BN / WN);
    const int m0 = blockIdx.x * BM;

    float acc[MT][NT][4];
    #pragma unroll
    for (int i = 0; i < MT; i++)
        #pragma unroll
        for (int j = 0; j < NT; j++)
            #pragma unroll
            for (int q = 0; q < 4; q++) acc[i][j][q] = 0.f;

    float4 regA[AL], regB[BL];

    // lane-derived ldmatrix addressing components
    const int arow = l & 15;                       // A tile row within 16
    const int acol = (l & 16) ? 16 : 0;            // A k8-group byte offset
    const int brow = ((l & 16) ? 8 : 0) + (l & 7); // B row (2 n8-tiles per x4)
    const int bcol = (l & 8) ? 16 : 0;             // B k8-group byte offset

    auto loadChunk = [&](int c) {
        const int k0 = c * 32;
        #pragma unroll
        for (int i = 0; i < AL; i++) {
            int idx = tid + i * THREADS;
            int r = idx >> 3, c4 = (idx & 7) << 2;
            int row = m0 + r; if (row >= M) row = M - 1;
            regA[i] = __ldg((const float4*)(A + (size_t)row * K + k0 + c4));
        }
        #pragma unroll
        for (int i = 0; i < BL; i++) {
            int idx = tid + i * THREADS;
            int r = idx >> 3, c4 = (idx & 7) << 2;
            regB[i] = __ldg((const float4*)(W + (size_t)r * K + k0 + c4));
        }
    };

    auto stsChunk = [&](int b) {
        char* abase = smem + b * (ASZ + BSZ);
        char* bbase = abase + ASZ;
        #pragma unroll
        for (int i = 0; i < AL; i++) {
            int idx = tid + i * THREADS;
            int r = idx >> 3, c4 = (idx & 7) << 2;
            uint2 hi, lo; cvt_hilo(regA[i], hi, lo);
            *(uint2*)(abase + sw128((uint32_t)(r * 128 + c4 * 2)))      = hi;
            *(uint2*)(abase + sw128((uint32_t)(r * 128 + 64 + c4 * 2))) = lo;
        }
        #pragma unroll
        for (int i = 0; i < BL; i++) {
            int idx = tid + i * THREADS;
            int r = idx >> 3, c4 = (idx & 7) << 2;
            uint2 hi, lo; cvt_hilo(regB[i], hi, lo);
            *(uint2*)(bbase + sw128((uint32_t)(r * 128 + c4 * 2)))      = hi;
            *(uint2*)(bbase + sw128((uint32_t)(r * 128 + 64 + c4 * 2))) = lo;
        }
    };

    auto compute = [&](int b) {
        const uint32_t sA = sb + b * (ASZ + BSZ);
        const uint32_t sB = sA + ASZ;
        #pragma unroll
        for (int kg = 0; kg < 2; kg++) {
            const int kb = kg * 32;
            uint32_t aH[MT][4], aLo[MT][4];
            #pragma unroll
            for (int mt = 0; mt < MT; mt++) {
                uint32_t rowb = (uint32_t)((wmBase + mt * 16 + arow) * 128);
                ldsm_x4(aH[mt],  sA + sw128(rowb + kb + acol));
                ldsm_x4(aLo[mt], sA + sw128(rowb + 64 + kb + acol));
            }
            uint32_t bH[NT][2], bLo[NT][2];
            #pragma unroll
            for (int nt = 0; nt < NT; nt += 2) {
                uint32_t rowb = (uint32_t)((wnBase + nt * 8 + brow) * 128);
                uint32_t t[4];
                ldsm_x4(t, sB + sw128(rowb + kb + bcol));
                bH[nt][0] = t[0]; bH[nt][1] = t[1];
                bH[nt + 1][0] = t[2]; bH[nt + 1][1] = t[3];
                ldsm_x4(t, sB + sw128(rowb + 64 + kb + bcol));
                bLo[nt][0] = t[0]; bLo[nt][1] = t[1];
                bLo[nt + 1][0] = t[2]; bLo[nt + 1][1] = t[3];
            }
            #pragma unroll
            for (int mt = 0; mt < MT; mt++)
                #pragma unroll
                for (int nt = 0; nt < NT; nt++) {
                    mma16816(acc[mt][nt], aH[mt],  bH[nt]);
                    mma16816(acc[mt][nt], aH[mt],  bLo[nt]);
                    mma16816(acc[mt][nt], aLo[mt], bH[nt]);
                }
        }
    };

    // prologue
    loadChunk(0);
    stsChunk(0);
    __syncthreads();

    for (int c = 0; c < NCHUNK; c++) {
        if (c + 1 < NCHUNK) loadChunk(c + 1);
        compute(c & 1);
        if (c + 1 < NCHUNK) {
            __syncthreads();          // everyone done reading buf (c+1)&1 from iter c-1
            stsChunk((c + 1) & 1);
            __syncthreads();
        }
    }

    // epilogue: write fp32 accumulators
    #pragma unroll
    for (int mt = 0; mt < MT; mt++) {
        int m = m0 + wmBase + mt * 16 + (l >> 2);
        #pragma unroll
        for (int nt = 0; nt < NT; nt++) {
            int nn = wnBase + nt * 8 + ((l & 3) << 1);
            if (m < M)
                *(float2*)(C + (size_t)m * BN + nn) =
                    make_float2(acc[mt][nt][0], acc[mt][nt][1]);
            if (m + 8 < M)
                *(float2*)(C + (size_t)(m + 8) * BN + nn) =
                    make_float2(acc[mt][nt][2], acc[mt][nt][3]);
        }
    }
}

// ---------------- SpMM (CSR, warp per row, packed edges, 2x unroll) --------
template <int WIDTH, bool RELU>
__global__ void spmm_kernel(const float* __restrict__ h,
                            float* __restrict__ out, int n) {
    int warp = (blockIdx.x * blockDim.x + threadIdx.x) >> 5;
    int lane = threadIdx.x & 31;
    if (warp >= n) return;
    int s = g_rowptr[warp];
    int e = g_rowptr[warp + 1];

    if (WIDTH == 128) {
        float4 acc = make_float4(0.f, 0.f, 0.f, 0.f);
        int i = s;
        for (; i + 2 <= e; i += 2) {
            int2 p0 = g_epack[i];
            int2 p1 = g_epack[i + 1];
            float v0 = __int_as_float(p0.y);
            float v1 = __int_as_float(p1.y);
            float4 h0 = __ldg((const float4*)(h + (size_t)p0.x * 128) + lane);
            float4 h1 = __ldg((const float4*)(h + (size_t)p1.x * 128) + lane);
            acc.x += v0 * h0.x; acc.y += v0 * h0.y;
            acc.z += v0 * h0.z; acc.w += v0 * h0.w;
            acc.x += v1 * h1.x; acc.y += v1 * h1.y;
            acc.z += v1 * h1.z; acc.w += v1 * h1.w;
        }
        if (i < e) {
            int2 p = g_epack[i];
            float v = __int_as_float(p.y);
            float4 hv = __ldg((const float4*)(h + (size_t)p.x * 128) + lane);
            acc.x += v * hv.x; acc.y += v * hv.y;
            acc.z += v * hv.z; acc.w += v * hv.w;
        }
        if (RELU) {
            acc.x = fmaxf(acc.x, 0.f); acc.y = fmaxf(acc.y, 0.f);
            acc.z = fmaxf(acc.z, 0.f); acc.w = fmaxf(acc.w, 0.f);
        }
        ((float4*)(out + (size_t)warp * 128))[lane] = acc;
    } else {  // WIDTH == 64
        float2 acc = make_float2(0.f, 0.f);
        int i = s;
        for (; i + 2 <= e; i += 2) {
            int2 p0 = g_epack[i];
            int2 p1 = g_epack[i + 1];
            float v0 = __int_as_float(p0.y);
            float v1 = __int_as_float(p1.y);
            float2 h0 = __ldg((const float2*)(h + (size_t)p0.x * 64) + lane);
            float2 h1 = __ldg((const float2*)(h + (size_t)p1.x * 64) + lane);
            acc.x += v0 * h0.x; acc.y += v0 * h0.y;
            acc.x += v1 * h1.x; acc.y += v1 * h1.y;
        }
        if (i < e) {
            int2 p = g_epack[i];
            float v = __int_as_float(p.y);
            float2 hv = __ldg((const float2*)(h + (size_t)p.x * 64) + lane);
            acc.x += v * hv.x; acc.y += v * hv.y;
        }
        if (RELU) { acc.x = fmaxf(acc.x, 0.f); acc.y = fmaxf(acc.y, 0.f); }
        ((float2*)(out + (size_t)warp * 64))[lane] = acc;
    }
}

// ---------------- Launcher ----------------
extern "C" void kernel_launch(void* const* d_in, const int* in_sizes, int n_in,
                              void* d_out, int out_size) {
    const float* x    = (const float*)d_in[0];
    const int*   rows = (const int*)  d_in[1];
    const int*   cols = (const int*)  d_in[2];
    const float* vals = (const float*)d_in[3];
    const float* W0   = (const float*)d_in[4];
    const float* W1   = (const float*)d_in[5];
    const float* W2   = (const float*)d_in[6];
    float* out = (float*)d_out;

    int n = in_sizes[0] / DIM_IN;   // 100000
    int E = in_sizes[1];            // 1600000
    int nb = (n + SCAN_BLK - 1) / SCAN_BLK;

    float* bufA; float* bufB;
    cudaGetSymbolAddress((void**)&bufA, g_bufA);
    cudaGetSymbolAddress((void**)&bufB, g_bufB);

    // smem: double-buffered (A + B) tiles
    const int smem0 = 2 * (128 * 128 + 128 * 128);  // 64 KB (BN=128)
    const int smem2 = 2 * (128 * 128 + 64 * 128);   // 48 KB (BN=64)
    cudaFuncSetAttribute(mma_gemm_kernel<128, 128, 2, 4, 512>,
                         cudaFuncAttributeMaxDynamicSharedMemorySize, smem0);
    cudaFuncSetAttribute(mma_gemm_kernel<128, 128, 2, 4, 128>,
                         cudaFuncAttributeMaxDynamicSharedMemorySize, smem0);
    cudaFuncSetAttribute(mma_gemm_kernel<128, 64, 4, 2, 128>,
                         cudaFuncAttributeMaxDynamicSharedMemorySize, smem2);

    // ---- CSR build (multi-block scan) ----
    zero_counts_kernel<<<(n + 255) / 256, 256>>>(n);
    hist_kernel<<<(E + 255) / 256, 256>>>(rows, E);
    scan_blocks_kernel<<<nb, SCAN_BLK>>>(n);
    scan_partials_kernel<<<1, 128>>>(nb, n);
    scan_add_kernel<<<nb, SCAN_BLK>>>(n);
    scatter_kernel<<<(E + 255) / 256, 256>>>(rows, cols, vals, E);

    int gemmGrid = (n + 127) / 128;
    int spmmGrid = (n + 7) / 8;     // 8 warps per 256-thread block

    // layer 0: x @ W0^T -> spmm -> relu
    mma_gemm_kernel<128, 128, 2, 4, 512><<<gemmGrid, 256, smem0>>>(x, W0, bufA, n);
    spmm_kernel<128, true><<<spmmGrid, 256>>>(bufA, bufB, n);

    // layer 1: h @ W1^T -> spmm -> relu
    mma_gemm_kernel<128, 128, 2, 4, 128><<<gemmGrid, 256, smem0>>>(bufB, W1, bufA, n);
    spmm_kernel<128, true><<<spmmGrid, 256>>>(bufA, bufB, n);

    // layer 2: h @ W2^T -> spmm (no relu)
    mma_gemm_kernel<128, 64, 4, 2, 128><<<gemmGrid, 256, smem2>>>(bufB, W2, bufA, n);
    spmm_kernel<64, false><<<spmmGrid, 256>>>(bufA, out, n);
}

// round 7
// speedup vs baseline: 1.3069x; 1.1212x over previous
#include <cuda_runtime.h>
#include <cuda_bf16.h>
#include <cuda_fp16.h>
#include <stdint.h>

// ---------------- Problem constants (fixed dataset) ----------------
#define NMAX 100000
#define EMAX 1600000
#define DIM_IN  512
#define DIM_HID 128
#define DIM_OUT 64

#define SCAN_BLK 1024

// ---------------- Device scratch (no allocations allowed) ----------------
__device__ float g_bufA[(size_t)NMAX * DIM_HID];   // gemm outputs (fp16 L0/L1, fp32 L2)
__device__ float g_bufB[(size_t)NMAX * DIM_HID];   // spmm outputs (fp32)
__device__ int   g_deg[NMAX];
__device__ int   g_cnt[NMAX];
__device__ int   g_rowptr[NMAX + 1];
__device__ int   g_blksum[128];
__device__ int2  g_epack[EMAX];                    // (col, val bits) per CSR slot

// ---------------- helpers ----------------
__device__ __forceinline__ uint32_t smem_u32(const void* p) {
    uint32_t a;
    asm("{ .reg .u64 t; cvta.to.shared.u64 t, %1; cvt.u32.u64 %0, t; }" : "=r"(a) : "l"(p));
    return a;
}
__device__ __forceinline__ uint32_t sw128(uint32_t b) { return b ^ ((b >> 3) & 0x70); }

__device__ __forceinline__ void ldsm_x4(uint32_t* r, uint32_t addr) {
    asm volatile("ldmatrix.sync.aligned.m8n8.x4.shared.b16 {%0,%1,%2,%3}, [%4];"
                 : "=r"(r[0]), "=r"(r[1]), "=r"(r[2]), "=r"(r[3]) : "r"(addr));
}
__device__ __forceinline__ void mma16816(float* d, const uint32_t* a, const uint32_t* b) {
    asm volatile(
        "mma.sync.aligned.m16n8k16.row.col.f32.bf16.bf16.f32 "
        "{%0,%1,%2,%3}, {%4,%5,%6,%7}, {%8,%9}, {%0,%1,%2,%3};"
        : "+f"(d[0]), "+f"(d[1]), "+f"(d[2]), "+f"(d[3])
        : "r"(a[0]), "r"(a[1]), "r"(a[2]), "r"(a[3]), "r"(b[0]), "r"(b[1]));
}

// fp32 -> (hi, lo) bf16 pairs, 4 floats at a time
__device__ __forceinline__ void cvt_hilo(float4 v, uint2& hi, uint2& lo) {
    __nv_bfloat162 h01 = __floats2bfloat162_rn(v.x, v.y);
    __nv_bfloat162 h23 = __floats2bfloat162_rn(v.z, v.w);
    __nv_bfloat162 l01 = __floats2bfloat162_rn(v.x - __bfloat162float(h01.x),
                                               v.y - __bfloat162float(h01.y));
    __nv_bfloat162 l23 = __floats2bfloat162_rn(v.z - __bfloat162float(h23.x),
                                               v.w - __bfloat162float(h23.y));
    hi = make_uint2(*(uint32_t*)&h01, *(uint32_t*)&h23);
    lo = make_uint2(*(uint32_t*)&l01, *(uint32_t*)&l23);
}

// ---------------- CSR build ----------------
__global__ void zero_counts_kernel(int n) {
    int i = blockIdx.x * blockDim.x + threadIdx.x;
    if (i < n) { g_deg[i] = 0; g_cnt[i] = 0; }
}

__global__ void hist_kernel(const int* __restrict__ rows, int E) {
    int i = blockIdx.x * blockDim.x + threadIdx.x;
    if (i < E) atomicAdd(&g_deg[rows[i]], 1);
}

// Phase A: per-block scan of 1024 degrees; local exclusive prefix + block total.
__global__ void scan_blocks_kernel(int n) {
    __shared__ int warpsums[32];
    int tid = threadIdx.x, lane = tid & 31, wid = tid >> 5;
    int i = blockIdx.x * SCAN_BLK + tid;
    int v = (i < n) ? g_deg[i] : 0;
    int x = v;
    #pragma unroll
    for (int o = 1; o < 32; o <<= 1) {
        int y = __shfl_up_sync(0xffffffffu, x, o);
        if (lane >= o) x += y;
    }
    if (lane == 31) warpsums[wid] = x;
    __syncthreads();
    if (wid == 0) {
        int s = warpsums[lane];
        #pragma unroll
        for (int o = 1; o < 32; o <<= 1) {
            int y = __shfl_up_sync(0xffffffffu, s, o);
            if (lane >= o) s += y;
        }
        warpsums[lane] = s;
    }
    __syncthreads();
    int pref = (wid > 0) ? warpsums[wid - 1] : 0;
    int incl = x + pref;
    if (i < n) g_rowptr[i] = incl - v;     // block-local exclusive prefix
    if (tid == SCAN_BLK - 1) g_blksum[blockIdx.x] = incl;
}

// Phase B: one 128-thread block scans the (<=128) block totals, exclusive.
__global__ void scan_partials_kernel(int nb, int n) {
    __shared__ int warpsums[4];
    int tid = threadIdx.x, lane = tid & 31, wid = tid >> 5;
    int v = (tid < nb) ? g_blksum[tid] : 0;
    int x = v;
    #pragma unroll
    for (int o = 1; o < 32; o <<= 1) {
        int y = __shfl_up_sync(0xffffffffu, x, o);
        if (lane >= o) x += y;
    }
    if (lane == 31) warpsums[wid] = x;
    __syncthreads();
    if (tid == 0) {
        int c = 0;
        #pragma unroll
        for (int q = 0; q < 4; q++) { int t = warpsums[q]; warpsums[q] = c; c += t; }
    }
    __syncthreads();
    int incl = x + warpsums[wid];
    if (tid < nb) g_blksum[tid] = incl - v;   // exclusive block offsets
    if (tid == nb - 1) g_rowptr[n] = incl;    // grand total
}

// Phase C: add block offsets.
__global__ void scan_add_kernel(int n) {
    int i = blockIdx.x * SCAN_BLK + threadIdx.x;
    if (i < n) g_rowptr[i] += g_blksum[blockIdx.x];
}

__global__ void scatter_kernel(const int* __restrict__ rows,
                               const int* __restrict__ cols,
                               const float* __restrict__ vals, int E) {
    int i = blockIdx.x * blockDim.x + threadIdx.x;
    if (i < E) {
        int r = rows[i];
        int p = g_rowptr[r] + atomicAdd(&g_cnt[r], 1);
        g_epack[p] = make_int2(cols[i], __float_as_int(vals[i]));
    }
}

// ---------------- Tensor-core GEMM via mma.sync ----------------
// C[M,BN] = A[M,K] * W[BN,K]^T, fp32 emulated by bf16 hi/lo split:
//   D += Ahi*Bhi + Ahi*Blo + Alo*Bhi   (error ~2^-16)
// smem rows = 128 bytes: [hi 32xbf16 | lo 32xbf16], SW128, double-buffered.
// HALFOUT: write result as fp16 (feeds the fp16-gather SpMM).
template <int BM, int BN, int WM, int WN, int K, bool HALFOUT>
__global__ void __launch_bounds__(WM * WN * 32, 1)
mma_gemm_kernel(const float* __restrict__ A, const float* __restrict__ W,
                void* __restrict__ Cv, int M)
{
    constexpr int THREADS = WM * WN * 32;
    constexpr int NCHUNK  = K / 32;
    constexpr int ASZ = BM * 128;
    constexpr int BSZ = BN * 128;
    constexpr int AL  = BM * 8 / THREADS;
    constexpr int BL  = BN * 8 / THREADS;
    constexpr int MT  = BM / WM / 16;
    constexpr int NT  = BN / WN / 8;

    extern __shared__ __align__(1024) char smem[];
    const uint32_t sb = smem_u32(smem);

    const int tid = threadIdx.x;
    const int l   = tid & 31;
    const int w   = tid >> 5;
    const int wmBase = (w % WM) * (BM / WM);
    const int wnBase = (w / WM) * (BN / WN);
    const int m0 = blockIdx.x * BM;

    float acc[MT][NT][4];
    #pragma unroll
    for (int i = 0; i < MT; i++)
        #pragma unroll
        for (int j = 0; j < NT; j++)
            #pragma unroll
            for (int q = 0; q < 4; q++) acc[i][j][q] = 0.f;

    float4 regA[AL], regB[BL];

    const int arow = l & 15;
    const int acol = (l & 16) ? 16 : 0;
    const int brow = ((l & 16) ? 8 : 0) + (l & 7);
    const int bcol = (l & 8) ? 16 : 0;

    auto loadChunk = [&](int c) {
        const int k0 = c * 32;
        #pragma unroll
        for (int i = 0; i < AL; i++) {
            int idx = tid + i * THREADS;
            int r = idx >> 3, c4 = (idx & 7) << 2;
            int row = m0 + r; if (row >= M) row = M - 1;
            regA[i] = __ldg((const float4*)(A + (size_t)row * K + k0 + c4));
        }
        #pragma unroll
        for (int i = 0; i < BL; i++) {
            int idx = tid + i * THREADS;
            int r = idx >> 3, c4 = (idx & 7) << 2;
            regB[i] = __ldg((const float4*)(W + (size_t)r * K + k0 + c4));
        }
    };

    auto stsChunk = [&](int b) {
        char* abase = smem + b * (ASZ + BSZ);
        char* bbase = abase + ASZ;
        #pragma unroll
        for (int i = 0; i < AL; i++) {
            int idx = tid + i * THREADS;
            int r = idx >> 3, c4 = (idx & 7) << 2;
            uint2 hi, lo; cvt_hilo(regA[i], hi, lo);
            *(uint2*)(abase + sw128((uint32_t)(r * 128 + c4 * 2)))      = hi;
            *(uint2*)(abase + sw128((uint32_t)(r * 128 + 64 + c4 * 2))) = lo;
        }
        #pragma unroll
        for (int i = 0; i < BL; i++) {
            int idx = tid + i * THREADS;
            int r = idx >> 3, c4 = (idx & 7) << 2;
            uint2 hi, lo; cvt_hilo(regB[i], hi, lo);
            *(uint2*)(bbase + sw128((uint32_t)(r * 128 + c4 * 2)))      = hi;
            *(uint2*)(bbase + sw128((uint32_t)(r * 128 + 64 + c4 * 2))) = lo;
        }
    };

    auto compute = [&](int b) {
        const uint32_t sA = sb + b * (ASZ + BSZ);
        const uint32_t sB = sA + ASZ;
        #pragma unroll
        for (int kg = 0; kg < 2; kg++) {
            const int kb = kg * 32;
            uint32_t aH[MT][4], aLo[MT][4];
            #pragma unroll
            for (int mt = 0; mt < MT; mt++) {
                uint32_t rowb = (uint32_t)((wmBase + mt * 16 + arow) * 128);
                ldsm_x4(aH[mt],  sA + sw128(rowb + kb + acol));
                ldsm_x4(aLo[mt], sA + sw128(rowb + 64 + kb + acol));
            }
            uint32_t bH[NT][2], bLo[NT][2];
            #pragma unroll
            for (int nt = 0; nt < NT; nt += 2) {
                uint32_t rowb = (uint32_t)((wnBase + nt * 8 + brow) * 128);
                uint32_t t[4];
                ldsm_x4(t, sB + sw128(rowb + kb + bcol));
                bH[nt][0] = t[0]; bH[nt][1] = t[1];
                bH[nt + 1][0] = t[2]; bH[nt + 1][1] = t[3];
                ldsm_x4(t, sB + sw128(rowb + 64 + kb + bcol));
                bLo[nt][0] = t[0]; bLo[nt][1] = t[1];
                bLo[nt + 1][0] = t[2]; bLo[nt + 1][1] = t[3];
            }
            #pragma unroll
            for (int mt = 0; mt < MT; mt++)
                #pragma unroll
                for (int nt = 0; nt < NT; nt++) {
                    mma16816(acc[mt][nt], aH[mt],  bH[nt]);
                    mma16816(acc[mt][nt], aH[mt],  bLo[nt]);
                    mma16816(acc[mt][nt], aLo[mt], bH[nt]);
                }
        }
    };

    loadChunk(0);
    stsChunk(0);
    __syncthreads();

    for (int c = 0; c < NCHUNK; c++) {
        if (c + 1 < NCHUNK) loadChunk(c + 1);
        compute(c & 1);
        if (c + 1 < NCHUNK) {
            __syncthreads();
            stsChunk((c + 1) & 1);
            __syncthreads();
        }
    }

    // epilogue
    #pragma unroll
    for (int mt = 0; mt < MT; mt++) {
        int m = m0 + wmBase + mt * 16 + (l >> 2);
        #pragma unroll
        for (int nt = 0; nt < NT; nt++) {
            int nn = wnBase + nt * 8 + ((l & 3) << 1);
            if constexpr (HALFOUT) {
                __half* Ch = (__half*)Cv;
                if (m < M)
                    *(__half2*)(Ch + (size_t)m * BN + nn) =
                        __floats2half2_rn(acc[mt][nt][0], acc[mt][nt][1]);
                if (m + 8 < M)
                    *(__half2*)(Ch + (size_t)(m + 8) * BN + nn) =
                        __floats2half2_rn(acc[mt][nt][2], acc[mt][nt][3]);
            } else {
                float* C = (float*)Cv;
                if (m < M)
                    *(float2*)(C + (size_t)m * BN + nn) =
                        make_float2(acc[mt][nt][0], acc[mt][nt][1]);
                if (m + 8 < M)
                    *(float2*)(C + (size_t)(m + 8) * BN + nn) =
                        make_float2(acc[mt][nt][2], acc[mt][nt][3]);
            }
        }
    }
}

// ---------------- SpMM (CSR, warp per row, packed edges, 2x unroll) --------
// HALFIN: h is fp16 (256B/row gather instead of 512B); accumulate fp32.
template <int WIDTH, bool RELU, bool HALFIN>
__global__ void spmm_kernel(const void* __restrict__ hv,
                            float* __restrict__ out, int n) {
    int warp = (blockIdx.x * blockDim.x + threadIdx.x) >> 5;
    int lane = threadIdx.x & 31;
    if (warp >= n) return;
    int s = g_rowptr[warp];
    int e = g_rowptr[warp + 1];

    if (WIDTH == 128) {
        float4 acc = make_float4(0.f, 0.f, 0.f, 0.f);
        int i = s;
        if constexpr (HALFIN) {
            const __half* h = (const __half*)hv;
            for (; i + 2 <= e; i += 2) {
                int2 p0 = g_epack[i];
                int2 p1 = g_epack[i + 1];
                float v0 = __int_as_float(p0.y);
                float v1 = __int_as_float(p1.y);
                uint2 r0 = __ldg((const uint2*)(h + (size_t)p0.x * 128) + lane);
                uint2 r1 = __ldg((const uint2*)(h + (size_t)p1.x * 128) + lane);
                float2 a01 = __half22float2(*(__half2*)&r0.x);
                float2 a23 = __half22float2(*(__half2*)&r0.y);
                float2 b01 = __half22float2(*(__half2*)&r1.x);
                float2 b23 = __half22float2(*(__half2*)&r1.y);
                acc.x += v0 * a01.x; acc.y += v0 * a01.y;
                acc.z += v0 * a23.x; acc.w += v0 * a23.y;
                acc.x += v1 * b01.x; acc.y += v1 * b01.y;
                acc.z += v1 * b23.x; acc.w += v1 * b23.y;
            }
            if (i < e) {
                int2 p = g_epack[i];
                float v = __int_as_float(p.y);
                uint2 r0 = __ldg((const uint2*)(h + (size_t)p.x * 128) + lane);
                float2 a01 = __half22float2(*(__half2*)&r0.x);
                float2 a23 = __half22float2(*(__half2*)&r0.y);
                acc.x += v * a01.x; acc.y += v * a01.y;
                acc.z += v * a23.x; acc.w += v * a23.y;
            }
        } else {
            const float* h = (const float*)hv;
            for (; i + 2 <= e; i += 2) {
                int2 p0 = g_epack[i];
                int2 p1 = g_epack[i + 1];
                float v0 = __int_as_float(p0.y);
                float v1 = __int_as_float(p1.y);
                float4 h0 = __ldg((const float4*)(h + (size_t)p0.x * 128) + lane);
                float4 h1 = __ldg((const float4*)(h + (size_t)p1.x * 128) + lane);
                acc.x += v0 * h0.x; acc.y += v0 * h0.y;
                acc.z += v0 * h0.z; acc.w += v0 * h0.w;
                acc.x += v1 * h1.x; acc.y += v1 * h1.y;
                acc.z += v1 * h1.z; acc.w += v1 * h1.w;
            }
            if (i < e) {
                int2 p = g_epack[i];
                float v = __int_as_float(p.y);
                float4 hvv = __ldg((const float4*)(h + (size_t)p.x * 128) + lane);
                acc.x += v * hvv.x; acc.y += v * hvv.y;
                acc.z += v * hvv.z; acc.w += v * hvv.w;
            }
        }
        if (RELU) {
            acc.x = fmaxf(acc.x, 0.f); acc.y = fmaxf(acc.y, 0.f);
            acc.z = fmaxf(acc.z, 0.f); acc.w = fmaxf(acc.w, 0.f);
        }
        ((float4*)(out + (size_t)warp * 128))[lane] = acc;
    } else {  // WIDTH == 64, fp32 in
        const float* h = (const float*)hv;
        float2 acc = make_float2(0.f, 0.f);
        int i = s;
        for (; i + 2 <= e; i += 2) {
            int2 p0 = g_epack[i];
            int2 p1 = g_epack[i + 1];
            float v0 = __int_as_float(p0.y);
            float v1 = __int_as_float(p1.y);
            float2 h0 = __ldg((const float2*)(h + (size_t)p0.x * 64) + lane);
            float2 h1 = __ldg((const float2*)(h + (size_t)p1.x * 64) + lane);
            acc.x += v0 * h0.x; acc.y += v0 * h0.y;
            acc.x += v1 * h1.x; acc.y += v1 * h1.y;
        }
        if (i < e) {
            int2 p = g_epack[i];
            float v = __int_as_float(p.y);
            float2 hvv = __ldg((const float2*)(h + (size_t)p.x * 64) + lane);
            acc.x += v * hvv.x; acc.y += v * hvv.y;
        }
        if (RELU) { acc.x = fmaxf(acc.x, 0.f); acc.y = fmaxf(acc.y, 0.f); }
        ((float2*)(out + (size_t)warp * 64))[lane] = acc;
    }
}

// ---------------- Launcher ----------------
extern "C" void kernel_launch(void* const* d_in, const int* in_sizes, int n_in,
                              void* d_out, int out_size) {
    const float* x    = (const float*)d_in[0];
    const int*   rows = (const int*)  d_in[1];
    const int*   cols = (const int*)  d_in[2];
    const float* vals = (const float*)d_in[3];
    const float* W0   = (const float*)d_in[4];
    const float* W1   = (const float*)d_in[5];
    const float* W2   = (const float*)d_in[6];
    float* out = (float*)d_out;

    int n = in_sizes[0] / DIM_IN;   // 100000
    int E = in_sizes[1];            // 1600000
    int nb = (n + SCAN_BLK - 1) / SCAN_BLK;

    float* bufA; float* bufB;
    cudaGetSymbolAddress((void**)&bufA, g_bufA);
    cudaGetSymbolAddress((void**)&bufB, g_bufB);

    const int smem0 = 2 * (128 * 128 + 128 * 128);  // 64 KB (BN=128)
    const int smem2 = 2 * (128 * 128 + 64 * 128);   // 48 KB (BN=64)
    cudaFuncSetAttribute(mma_gemm_kernel<128, 128, 2, 4, 512, true>,
                         cudaFuncAttributeMaxDynamicSharedMemorySize, smem0);
    cudaFuncSetAttribute(mma_gemm_kernel<128, 128, 2, 4, 128, true>,
                         cudaFuncAttributeMaxDynamicSharedMemorySize, smem0);
    cudaFuncSetAttribute(mma_gemm_kernel<128, 64, 4, 2, 128, false>,
                         cudaFuncAttributeMaxDynamicSharedMemorySize, smem2);

    // ---- CSR build (multi-block scan) ----
    zero_counts_kernel<<<(n + 255) / 256, 256>>>(n);
    hist_kernel<<<(E + 255) / 256, 256>>>(rows, E);
    scan_blocks_kernel<<<nb, SCAN_BLK>>>(n);
    scan_partials_kernel<<<1, 128>>>(nb, n);
    scan_add_kernel<<<nb, SCAN_BLK>>>(n);
    scatter_kernel<<<(E + 255) / 256, 256>>>(rows, cols, vals, E);

    int gemmGrid = (n + 127) / 128;
    int spmmGrid = (n + 7) / 8;     // 8 warps per 256-thread block

    // layer 0: x @ W0^T (fp16 out) -> spmm fp16-gather -> relu (fp32 out)
    mma_gemm_kernel<128, 128, 2, 4, 512, true><<<gemmGrid, 256, smem0>>>(x, W0, bufA, n);
    spmm_kernel<128, true, true><<<spmmGrid, 256>>>(bufA, bufB, n);

    // layer 1: h @ W1^T (fp16 out) -> spmm fp16-gather -> relu (fp32 out)
    mma_gemm_kernel<128, 128, 2, 4, 128, true><<<gemmGrid, 256, smem0>>>(bufB, W1, bufA, n);
    spmm_kernel<128, true, true><<<spmmGrid, 256>>>(bufA, bufB, n);

    // layer 2: h @ W2^T (fp32 out) -> spmm fp32 (no relu)
    mma_gemm_kernel<128, 64, 4, 2, 128, false><<<gemmGrid, 256, smem2>>>(bufB, W2, bufA, n);
    spmm_kernel<64, false, false><<<spmmGrid, 256>>>(bufA, out, n);
}

// round 8
// speedup vs baseline: 1.4730x; 1.1271x over previous
#include <cuda_runtime.h>
#include <cuda_fp16.h>
#include <stdint.h>

// ---------------- Problem constants (fixed dataset) ----------------
#define NMAX 100000
#define EMAX 1600000
#define DIM_IN  512
#define DIM_HID 128
#define DIM_OUT 64

#define SCAN_BLK 1024

// ---------------- Device scratch (no allocations allowed) ----------------
__device__ float g_bufA[(size_t)NMAX * DIM_HID];   // gemm outputs (fp16 stored)
__device__ float g_bufB[(size_t)NMAX * DIM_HID];   // spmm outputs (fp32)
__device__ int   g_deg[NMAX];
__device__ int   g_cnt[NMAX];
__device__ int   g_rowptr[NMAX + 1];
__device__ int   g_blksum[128];
__device__ int2  g_epack[EMAX];                    // (col, val bits) per CSR slot

// ---------------- helpers ----------------
__device__ __forceinline__ uint32_t smem_u32(const void* p) {
    uint32_t a;
    asm("{ .reg .u64 t; cvta.to.shared.u64 t, %1; cvt.u32.u64 %0, t; }" : "=r"(a) : "l"(p));
    return a;
}
__device__ __forceinline__ uint32_t sw128(uint32_t b) { return b ^ ((b >> 3) & 0x70); }

__device__ __forceinline__ void ldsm_x4(uint32_t* r, uint32_t addr) {
    asm volatile("ldmatrix.sync.aligned.m8n8.x4.shared.b16 {%0,%1,%2,%3}, [%4];"
                 : "=r"(r[0]), "=r"(r[1]), "=r"(r[2]), "=r"(r[3]) : "r"(addr));
}
// fp16 MMA, fp32 accumulate
__device__ __forceinline__ void mma16816(float* d, const uint32_t* a, const uint32_t* b) {
    asm volatile(
        "mma.sync.aligned.m16n8k16.row.col.f32.f16.f16.f32 "
        "{%0,%1,%2,%3}, {%4,%5,%6,%7}, {%8,%9}, {%0,%1,%2,%3};"
        : "+f"(d[0]), "+f"(d[1]), "+f"(d[2]), "+f"(d[3])
        : "r"(a[0]), "r"(a[1]), "r"(a[2]), "r"(a[3]), "r"(b[0]), "r"(b[1]));
}

// fp32x4 -> fp16 hi (uint2), and lo residual (uint2)
__device__ __forceinline__ uint2 cvt_hi(float4 v) {
    __half2 h01 = __floats2half2_rn(v.x, v.y);
    __half2 h23 = __floats2half2_rn(v.z, v.w);
    return make_uint2(*(uint32_t*)&h01, *(uint32_t*)&h23);
}
__device__ __forceinline__ uint2 cvt_lo(float4 v, uint2 hi) {
    __half2 h01 = *(__half2*)&hi.x;
    __half2 h23 = *(__half2*)&hi.y;
    float2 f01 = __half22float2(h01);
    float2 f23 = __half22float2(h23);
    __half2 l01 = __floats2half2_rn(v.x - f01.x, v.y - f01.y);
    __half2 l23 = __floats2half2_rn(v.z - f23.x, v.w - f23.y);
    return make_uint2(*(uint32_t*)&l01, *(uint32_t*)&l23);
}

// ---------------- CSR build ----------------
__global__ void zero_counts_kernel(int n) {
    int i = blockIdx.x * blockDim.x + threadIdx.x;
    if (i < n) { g_deg[i] = 0; g_cnt[i] = 0; }
}

__global__ void hist_kernel(const int* __restrict__ rows, int E) {
    int i = blockIdx.x * blockDim.x + threadIdx.x;
    if (i < E) atomicAdd(&g_deg[rows[i]], 1);
}

__global__ void scan_blocks_kernel(int n) {
    __shared__ int warpsums[32];
    int tid = threadIdx.x, lane = tid & 31, wid = tid >> 5;
    int i = blockIdx.x * SCAN_BLK + tid;
    int v = (i < n) ? g_deg[i] : 0;
    int x = v;
    #pragma unroll
    for (int o = 1; o < 32; o <<= 1) {
        int y = __shfl_up_sync(0xffffffffu, x, o);
        if (lane >= o) x += y;
    }
    if (lane == 31) warpsums[wid] = x;
    __syncthreads();
    if (wid == 0) {
        int s = warpsums[lane];
        #pragma unroll
        for (int o = 1; o < 32; o <<= 1) {
            int y = __shfl_up_sync(0xffffffffu, s, o);
            if (lane >= o) s += y;
        }
        warpsums[lane] = s;
    }
    __syncthreads();
    int pref = (wid > 0) ? warpsums[wid - 1] : 0;
    int incl = x + pref;
    if (i < n) g_rowptr[i] = incl - v;
    if (tid == SCAN_BLK - 1) g_blksum[blockIdx.x] = incl;
}

__global__ void scan_partials_kernel(int nb, int n) {
    __shared__ int warpsums[4];
    int tid = threadIdx.x, lane = tid & 31, wid = tid >> 5;
    int v = (tid < nb) ? g_blksum[tid] : 0;
    int x = v;
    #pragma unroll
    for (int o = 1; o < 32; o <<= 1) {
        int y = __shfl_up_sync(0xffffffffu, x, o);
        if (lane >= o) x += y;
    }
    if (lane == 31) warpsums[wid] = x;
    __syncthreads();
    if (tid == 0) {
        int c = 0;
        #pragma unroll
        for (int q = 0; q < 4; q++) { int t = warpsums[q]; warpsums[q] = c; c += t; }
    }
    __syncthreads();
    int incl = x + warpsums[wid];
    if (tid < nb) g_blksum[tid] = incl - v;
    if (tid == nb - 1) g_rowptr[n] = incl;
}

__global__ void scan_add_kernel(int n) {
    int i = blockIdx.x * SCAN_BLK + threadIdx.x;
    if (i < n) g_rowptr[i] += g_blksum[blockIdx.x];
}

__global__ void scatter_kernel(const int* __restrict__ rows,
                               const int* __restrict__ cols,
                               const float* __restrict__ vals, int E) {
    int i = blockIdx.x * blockDim.x + threadIdx.x;
    if (i < E) {
        int r = rows[i];
        int p = g_rowptr[r] + atomicAdd(&g_cnt[r], 1);
        g_epack[p] = make_int2(cols[i], __float_as_int(vals[i]));
    }
}

// ---------------- Tensor-core GEMM via fp16 mma.sync ----------------
// C[M,BN] = A[M,K] * W[BN,K]^T, fp32 emulated by fp16 split.
// TERMS=2: D += Ah*Bh + Ah*Bl  (A stored hi-only; error ~2^-12 RMS)
// TERMS=3: D += Ah*Bh + Ah*Bl + Al*Bh (error ~2^-22)
// K-chunk = 64 fp32 -> 128B fp16 rows, SW128 swizzle, double-buffered.
// Output written as fp16.
template <int BM, int BN, int WM, int WN, int K, int TERMS>
__global__ void __launch_bounds__(WM * WN * 32, 2)
mma_gemm_kernel(const float* __restrict__ A, const float* __restrict__ W,
                __half* __restrict__ C, int M)
{
    constexpr int THREADS = WM * WN * 32;
    constexpr int NCHUNK  = K / 64;
    constexpr int APL = (TERMS == 3) ? 2 : 1;    // A planes
    constexpr int ASZ = BM * 128;                // bytes per A plane
    constexpr int BSZ = BN * 128;                // bytes per B plane
    constexpr int BUF = APL * ASZ + 2 * BSZ;     // bytes per stage
    constexpr int AL  = BM * 16 / THREADS;       // float4 loads per thread (A)
    constexpr int BL  = BN * 16 / THREADS;       // float4 loads per thread (B)
    constexpr int MT  = BM / WM / 16;
    constexpr int NT  = BN / WN / 8;

    extern __shared__ __align__(1024) char smem[];
    const uint32_t sb = smem_u32(smem);

    const int tid = threadIdx.x;
    const int l   = tid & 31;
    const int w   = tid >> 5;
    const int wmBase = (w % WM) * (BM / WM);
    const int wnBase = (w / WM) * (BN / WN);
    const int m0 = blockIdx.x * BM;

    float acc[MT][NT][4];
    #pragma unroll
    for (int i = 0; i < MT; i++)
        #pragma unroll
        for (int j = 0; j < NT; j++)
            #pragma unroll
            for (int q = 0; q < 4; q++) acc[i][j][q] = 0.f;

    uint2 regAh[AL], regAl[(TERMS == 3) ? AL : 1];
    uint2 regBh[BL], regBl[BL];

    const int arow = l & 15;
    const int acol = (l & 16) ? 16 : 0;
    const int brow = ((l & 16) ? 8 : 0) + (l & 7);
    const int bcol = (l & 8) ? 16 : 0;

    auto loadChunk = [&](int c) {
        const int k0 = c * 64;
        #pragma unroll
        for (int i = 0; i < AL; i++) {
            int idx = tid + i * THREADS;
            int r = idx >> 4, c4 = (idx & 15) << 2;
            int row = m0 + r; if (row >= M) row = M - 1;
            float4 v = __ldg((const float4*)(A + (size_t)row * K + k0 + c4));
            regAh[i] = cvt_hi(v);
            if constexpr (TERMS == 3) regAl[i] = cvt_lo(v, regAh[i]);
        }
        #pragma unroll
        for (int i = 0; i < BL; i++) {
            int idx = tid + i * THREADS;
            int r = idx >> 4, c4 = (idx & 15) << 2;
            float4 v = __ldg((const float4*)(W + (size_t)r * K + k0 + c4));
            regBh[i] = cvt_hi(v);
            regBl[i] = cvt_lo(v, regBh[i]);
        }
    };

    auto stsChunk = [&](int b) {
        char* base  = smem + b * BUF;
        char* aHi   = base;
        char* aLo   = base + ASZ;                 // only if TERMS==3
        char* bHi   = base + APL * ASZ;
        char* bLo   = bHi + BSZ;
        #pragma unroll
        for (int i = 0; i < AL; i++) {
            int idx = tid + i * THREADS;
            int r = idx >> 4, c4 = (idx & 15) << 2;
            uint32_t off = sw128((uint32_t)(r * 128 + c4 * 2));
            *(uint2*)(aHi + off) = regAh[i];
            if constexpr (TERMS == 3) *(uint2*)(aLo + off) = regAl[i];
        }
        #pragma unroll
        for (int i = 0; i < BL; i++) {
            int idx = tid + i * THREADS;
            int r = idx >> 4, c4 = (idx & 15) << 2;
            uint32_t off = sw128((uint32_t)(r * 128 + c4 * 2));
            *(uint2*)(bHi + off) = regBh[i];
            *(uint2*)(bLo + off) = regBl[i];
        }
    };

    auto compute = [&](int b) {
        const uint32_t sAhi = sb + b * BUF;
        const uint32_t sAlo = sAhi + ASZ;
        const uint32_t sBhi = sAhi + APL * ASZ;
        const uint32_t sBlo = sBhi + BSZ;
        #pragma unroll
        for (int kb = 0; kb < 4; kb++) {
            const int kboff = kb * 32;
            uint32_t aH[MT][4], aLo[(TERMS == 3) ? MT : 1][4];
            #pragma unroll
            for (int mt = 0; mt < MT; mt++) {
                uint32_t rowb = (uint32_t)((wmBase + mt * 16 + arow) * 128);
                ldsm_x4(aH[mt], sAhi + sw128(rowb + kboff + acol));
                if constexpr (TERMS == 3)
                    ldsm_x4(aLo[mt], sAlo + sw128(rowb + kboff + acol));
            }
            uint32_t bH[NT][2], bLo[NT][2];
            #pragma unroll
            for (int nt = 0; nt < NT; nt += 2) {
                uint32_t rowb = (uint32_t)((wnBase + nt * 8 + brow) * 128);
                uint32_t t[4];
                ldsm_x4(t, sBhi + sw128(rowb + kboff + bcol));
                bH[nt][0] = t[0]; bH[nt][1] = t[1];
                bH[nt + 1][0] = t[2]; bH[nt + 1][1] = t[3];
                ldsm_x4(t, sBlo + sw128(rowb + kboff + bcol));
                bLo[nt][0] = t[0]; bLo[nt][1] = t[1];
                bLo[nt + 1][0] = t[2]; bLo[nt + 1][1] = t[3];
            }
            #pragma unroll
            for (int mt = 0; mt < MT; mt++)
                #pragma unroll
                for (int nt = 0; nt < NT; nt++) {
                    mma16816(acc[mt][nt], aH[mt], bH[nt]);
                    mma16816(acc[mt][nt], aH[mt], bLo[nt]);
                    if constexpr (TERMS == 3)
                        mma16816(acc[mt][nt], aLo[mt], bH[nt]);
                }
        }
    };

    loadChunk(0);
    stsChunk(0);
    __syncthreads();

    for (int c = 0; c < NCHUNK; c++) {
        if (c + 1 < NCHUNK) loadChunk(c + 1);
        compute(c & 1);
        if (c + 1 < NCHUNK) {
            __syncthreads();
            stsChunk((c + 1) & 1);
            __syncthreads();
        }
    }

    // epilogue: fp16 out
    #pragma unroll
    for (int mt = 0; mt < MT; mt++) {
        int m = m0 + wmBase + mt * 16 + (l >> 2);
        #pragma unroll
        for (int nt = 0; nt < NT; nt++) {
            int nn = wnBase + nt * 8 + ((l & 3) << 1);
            if (m < M)
                *(__half2*)(C + (size_t)m * BN + nn) =
                    __floats2half2_rn(acc[mt][nt][0], acc[mt][nt][1]);
            if (m + 8 < M)
                *(__half2*)(C + (size_t)(m + 8) * BN + nn) =
                    __floats2half2_rn(acc[mt][nt][2], acc[mt][nt][3]);
        }
    }
}

// ---------------- SpMM (CSR, warp per row, fp16 gather, 2x unroll) ---------
// h is fp16, WIDTH elems/row; accumulate fp32; out fp32.
template <int WIDTH, bool RELU>
__global__ void spmm_kernel(const __half* __restrict__ h,
                            float* __restrict__ out, int n) {
    int warp = (blockIdx.x * blockDim.x + threadIdx.x) >> 5;
    int lane = threadIdx.x & 31;
    if (warp >= n) return;
    int s = g_rowptr[warp];
    int e = g_rowptr[warp + 1];

    if (WIDTH == 128) {
        float4 acc = make_float4(0.f, 0.f, 0.f, 0.f);
        int i = s;
        for (; i + 2 <= e; i += 2) {
            int2 p0 = g_epack[i];
            int2 p1 = g_epack[i + 1];
            float v0 = __int_as_float(p0.y);
            float v1 = __int_as_float(p1.y);
            uint2 r0 = __ldg((const uint2*)(h + (size_t)p0.x * 128) + lane);
            uint2 r1 = __ldg((const uint2*)(h + (size_t)p1.x * 128) + lane);
            float2 a01 = __half22float2(*(__half2*)&r0.x);
            float2 a23 = __half22float2(*(__half2*)&r0.y);
            float2 b01 = __half22float2(*(__half2*)&r1.x);
            float2 b23 = __half22float2(*(__half2*)&r1.y);
            acc.x += v0 * a01.x; acc.y += v0 * a01.y;
            acc.z += v0 * a23.x; acc.w += v0 * a23.y;
            acc.x += v1 * b01.x; acc.y += v1 * b01.y;
            acc.z += v1 * b23.x; acc.w += v1 * b23.y;
        }
        if (i < e) {
            int2 p = g_epack[i];
            float v = __int_as_float(p.y);
            uint2 r0 = __ldg((const uint2*)(h + (size_t)p.x * 128) + lane);
            float2 a01 = __half22float2(*(__half2*)&r0.x);
            float2 a23 = __half22float2(*(__half2*)&r0.y);
            acc.x += v * a01.x; acc.y += v * a01.y;
            acc.z += v * a23.x; acc.w += v * a23.y;
        }
        if (RELU) {
            acc.x = fmaxf(acc.x, 0.f); acc.y = fmaxf(acc.y, 0.f);
            acc.z = fmaxf(acc.z, 0.f); acc.w = fmaxf(acc.w, 0.f);
        }
        ((float4*)(out + (size_t)warp * 128))[lane] = acc;
    } else {  // WIDTH == 64
        float2 acc = make_float2(0.f, 0.f);
        int i = s;
        for (; i + 2 <= e; i += 2) {
            int2 p0 = g_epack[i];
            int2 p1 = g_epack[i + 1];
            float v0 = __int_as_float(p0.y);
            float v1 = __int_as_float(p1.y);
            uint32_t r0 = __ldg((const uint32_t*)(h + (size_t)p0.x * 64) + lane);
            uint32_t r1 = __ldg((const uint32_t*)(h + (size_t)p1.x * 64) + lane);
            float2 a = __half22float2(*(__half2*)&r0);
            float2 b = __half22float2(*(__half2*)&r1);
            acc.x += v0 * a.x; acc.y += v0 * a.y;
            acc.x += v1 * b.x; acc.y += v1 * b.y;
        }
        if (i < e) {
            int2 p = g_epack[i];
            float v = __int_as_float(p.y);
            uint32_t r0 = __ldg((const uint32_t*)(h + (size_t)p.x * 64) + lane);
            float2 a = __half22float2(*(__half2*)&r0);
            acc.x += v * a.x; acc.y += v * a.y;
        }
        if (RELU) { acc.x = fmaxf(acc.x, 0.f); acc.y = fmaxf(acc.y, 0.f); }
        ((float2*)(out + (size_t)warp * 64))[lane] = acc;
    }
}

// ---------------- Launcher ----------------
extern "C" void kernel_launch(void* const* d_in, const int* in_sizes, int n_in,
                              void* d_out, int out_size) {
    const float* x    = (const float*)d_in[0];
    const int*   rows = (const int*)  d_in[1];
    const int*   cols = (const int*)  d_in[2];
    const float* vals = (const float*)d_in[3];
    const float* W0   = (const float*)d_in[4];
    const float* W1   = (const float*)d_in[5];
    const float* W2   = (const float*)d_in[6];
    float* out = (float*)d_out;

    int n = in_sizes[0] / DIM_IN;   // 100000
    int E = in_sizes[1];            // 1600000
    int nb = (n + SCAN_BLK - 1) / SCAN_BLK;

    float* bufA; float* bufB;
    cudaGetSymbolAddress((void**)&bufA, g_bufA);
    cudaGetSymbolAddress((void**)&bufB, g_bufB);
    __half* bufAh = (__half*)bufA;

    // smem per stage: TERMS=2,BN=128: 16K + 32K = 48K; TERMS=3,BN=64: 32K + 16K = 48K.
    const int smemG = 2 * 48 * 1024;   // 96 KB double-buffered -> 2 CTAs/SM
    cudaFuncSetAttribute(mma_gemm_kernel<128, 128, 2, 4, 512, 2>,
                         cudaFuncAttributeMaxDynamicSharedMemorySize, smemG);
    cudaFuncSetAttribute(mma_gemm_kernel<128, 128, 2, 4, 128, 2>,
                         cudaFuncAttributeMaxDynamicSharedMemorySize, smemG);
    cudaFuncSetAttribute(mma_gemm_kernel<128, 64, 4, 2, 128, 3>,
                         cudaFuncAttributeMaxDynamicSharedMemorySize, smemG);

    // ---- CSR build (multi-block scan) ----
    zero_counts_kernel<<<(n + 255) / 256, 256>>>(n);
    hist_kernel<<<(E + 255) / 256, 256>>>(rows, E);
    scan_blocks_kernel<<<nb, SCAN_BLK>>>(n);
    scan_partials_kernel<<<1, 128>>>(nb, n);
    scan_add_kernel<<<nb, SCAN_BLK>>>(n);
    scatter_kernel<<<(E + 255) / 256, 256>>>(rows, cols, vals, E);

    int gemmGrid = (n + 127) / 128;
    int spmmGrid = (n + 7) / 8;

    // layer 0: x @ W0^T (fp16 out) -> spmm fp16 -> relu (fp32 out)
    mma_gemm_kernel<128, 128, 2, 4, 512, 2><<<gemmGrid, 256, smemG>>>(x, W0, bufAh, n);
    spmm_kernel<128, true><<<spmmGrid, 256>>>(bufAh, bufB, n);

    // layer 1: h @ W1^T (fp16 out) -> spmm fp16 -> relu (fp32 out)
    mma_gemm_kernel<128, 128, 2, 4, 128, 2><<<gemmGrid, 256, smemG>>>(bufB, W1, bufAh, n);
    spmm_kernel<128, true><<<spmmGrid, 256>>>(bufAh, bufB, n);

    // layer 2: h @ W2^T (fp16 out, 3-term for accuracy) -> spmm fp16 (no relu)
    mma_gemm_kernel<128, 64, 4, 2, 128, 3><<<gemmGrid, 256, smemG>>>(bufB, W2, bufAh, n);
    spmm_kernel<64, false><<<spmmGrid, 256>>>(bufAh, out, n);
}

// round 9
// speedup vs baseline: 1.5675x; 1.0642x over previous
#include <cuda_runtime.h>
#include <cuda_fp16.h>
#include <stdint.h>

// ---------------- Problem constants (fixed dataset) ----------------
#define NMAX 100000
#define EMAX 1600000
#define DIM_IN  512
#define DIM_HID 128
#define DIM_OUT 64

#define SCAN_BLK 1024

// ---------------- Device scratch (no allocations allowed) ----------------
__device__ float g_bufA[(size_t)NMAX * DIM_HID];   // gemm outputs (fp16 stored)
__device__ float g_bufB[(size_t)NMAX * DIM_HID];   // spmm outputs (fp16 stored)
__device__ int   g_deg[NMAX];
__device__ int   g_cnt[NMAX];
__device__ int   g_rowptr[NMAX + 1];
__device__ int   g_blksum[128];
__device__ int2  g_epack[EMAX];                    // (col, val bits) per CSR slot

// ---------------- helpers ----------------
__device__ __forceinline__ uint32_t smem_u32(const void* p) {
    uint32_t a;
    asm("{ .reg .u64 t; cvta.to.shared.u64 t, %1; cvt.u32.u64 %0, t; }" : "=r"(a) : "l"(p));
    return a;
}
__device__ __forceinline__ uint32_t sw128(uint32_t b) { return b ^ ((b >> 3) & 0x70); }

__device__ __forceinline__ void ldsm_x4(uint32_t* r, uint32_t addr) {
    asm volatile("ldmatrix.sync.aligned.m8n8.x4.shared.b16 {%0,%1,%2,%3}, [%4];"
                 : "=r"(r[0]), "=r"(r[1]), "=r"(r[2]), "=r"(r[3]) : "r"(addr));
}
// fp16 MMA, fp32 accumulate
__device__ __forceinline__ void mma16816(float* d, const uint32_t* a, const uint32_t* b) {
    asm volatile(
        "mma.sync.aligned.m16n8k16.row.col.f32.f16.f16.f32 "
        "{%0,%1,%2,%3}, {%4,%5,%6,%7}, {%8,%9}, {%0,%1,%2,%3};"
        : "+f"(d[0]), "+f"(d[1]), "+f"(d[2]), "+f"(d[3])
        : "r"(a[0]), "r"(a[1]), "r"(a[2]), "r"(a[3]), "r"(b[0]), "r"(b[1]));
}

__device__ __forceinline__ uint2 cvt_hi(float4 v) {
    __half2 h01 = __floats2half2_rn(v.x, v.y);
    __half2 h23 = __floats2half2_rn(v.z, v.w);
    return make_uint2(*(uint32_t*)&h01, *(uint32_t*)&h23);
}
__device__ __forceinline__ uint2 cvt_lo(float4 v, uint2 hi) {
    float2 f01 = __half22float2(*(__half2*)&hi.x);
    float2 f23 = __half22float2(*(__half2*)&hi.y);
    __half2 l01 = __floats2half2_rn(v.x - f01.x, v.y - f01.y);
    __half2 l23 = __floats2half2_rn(v.z - f23.x, v.w - f23.y);
    return make_uint2(*(uint32_t*)&l01, *(uint32_t*)&l23);
}

// ---------------- CSR build ----------------
__global__ void zero_counts_kernel(int n) {
    int i = blockIdx.x * blockDim.x + threadIdx.x;
    if (i < n) { g_deg[i] = 0; g_cnt[i] = 0; }
}

__global__ void hist_kernel(const int* __restrict__ rows, int E) {
    int i = blockIdx.x * blockDim.x + threadIdx.x;
    if (i < E) atomicAdd(&g_deg[rows[i]], 1);
}

__global__ void scan_blocks_kernel(int n) {
    __shared__ int warpsums[32];
    int tid = threadIdx.x, lane = tid & 31, wid = tid >> 5;
    int i = blockIdx.x * SCAN_BLK + tid;
    int v = (i < n) ? g_deg[i] : 0;
    int x = v;
    #pragma unroll
    for (int o = 1; o < 32; o <<= 1) {
        int y = __shfl_up_sync(0xffffffffu, x, o);
        if (lane >= o) x += y;
    }
    if (lane == 31) warpsums[wid] = x;
    __syncthreads();
    if (wid == 0) {
        int s = warpsums[lane];
        #pragma unroll
        for (int o = 1; o < 32; o <<= 1) {
            int y = __shfl_up_sync(0xffffffffu, s, o);
            if (lane >= o) s += y;
        }
        warpsums[lane] = s;
    }
    __syncthreads();
    int pref = (wid > 0) ? warpsums[wid - 1] : 0;
    int incl = x + pref;
    if (i < n) g_rowptr[i] = incl - v;
    if (tid == SCAN_BLK - 1) g_blksum[blockIdx.x] = incl;
}

__global__ void scan_partials_kernel(int nb, int n) {
    __shared__ int warpsums[4];
    int tid = threadIdx.x, lane = tid & 31, wid = tid >> 5;
    int v = (tid < nb) ? g_blksum[tid] : 0;
    int x = v;
    #pragma unroll
    for (int o = 1; o < 32; o <<= 1) {
        int y = __shfl_up_sync(0xffffffffu, x, o);
        if (lane >= o) x += y;
    }
    if (lane == 31) warpsums[wid] = x;
    __syncthreads();
    if (tid == 0) {
        int c = 0;
        #pragma unroll
        for (int q = 0; q < 4; q++) { int t = warpsums[q]; warpsums[q] = c; c += t; }
    }
    __syncthreads();
    int incl = x + warpsums[wid];
    if (tid < nb) g_blksum[tid] = incl - v;
    if (tid == nb - 1) g_rowptr[n] = incl;
}

__global__ void scan_add_kernel(int n) {
    int i = blockIdx.x * SCAN_BLK + threadIdx.x;
    if (i < n) g_rowptr[i] += g_blksum[blockIdx.x];
}

__global__ void scatter_kernel(const int* __restrict__ rows,
                               const int* __restrict__ cols,
                               const float* __restrict__ vals, int E) {
    int i = blockIdx.x * blockDim.x + threadIdx.x;
    if (i < E) {
        int r = rows[i];
        int p = g_rowptr[r] + atomicAdd(&g_cnt[r], 1);
        g_epack[p] = make_int2(cols[i], __float_as_int(vals[i]));
    }
}

// ---------------- Tensor-core GEMM via fp16 mma.sync ----------------
// C[M,BN] = A[M,K] * W[BN,K]^T, 2-term fp16 split: D += Ah*Bh + Ah*Bl.
// AHALF: A already fp16 (Ah == A exactly; smem fill is a straight copy).
// K-chunk = 64 -> 128B fp16 rows, SW128 swizzle, double-buffered. fp16 out.
template <int BM, int BN, int WM, int WN, int K, bool AHALF>
__global__ void __launch_bounds__(WM * WN * 32, 2)
mma_gemm_kernel(const void* __restrict__ Av, const float* __restrict__ W,
                __half* __restrict__ C, int M)
{
    constexpr int THREADS = WM * WN * 32;
    constexpr int NCHUNK  = K / 64;
    constexpr int ASZ = BM * 128;                // A plane bytes (hi only)
    constexpr int BSZ = BN * 128;                // per B plane
    constexpr int BUF = ASZ + 2 * BSZ;
    constexpr int ALF = BM * 16 / THREADS;       // float4 loads (fp32 A)
    constexpr int ALH = BM * 8 / THREADS;        // uint4 loads (fp16 A)
    constexpr int BL  = BN * 16 / THREADS;       // float4 loads (W)
    constexpr int MT  = BM / WM / 16;
    constexpr int NT  = BN / WN / 8;

    extern __shared__ __align__(1024) char smem[];
    const uint32_t sb = smem_u32(smem);

    const int tid = threadIdx.x;
    const int l   = tid & 31;
    const int w   = tid >> 5;
    const int wmBase = (w % WM) * (BM / WM);
    const int wnBase = (w / WM) * (BN / WN);
    const int m0 = blockIdx.x * BM;

    const float*  Af = (const float*)Av;
    const __half* Ah = (const __half*)Av;

    float acc[MT][NT][4];
    #pragma unroll
    for (int i = 0; i < MT; i++)
        #pragma unroll
        for (int j = 0; j < NT; j++)
            #pragma unroll
            for (int q = 0; q < 4; q++) acc[i][j][q] = 0.f;

    uint2 regAh[AHALF ? 1 : ALF];
    uint4 regAp[AHALF ? ALH : 1];
    uint2 regBh[BL], regBl[BL];

    const int arow = l & 15;
    const int acol = (l & 16) ? 16 : 0;
    const int brow = ((l & 16) ? 8 : 0) + (l & 7);
    const int bcol = (l & 8) ? 16 : 0;

    auto loadChunk = [&](int c) {
        const int k0 = c * 64;
        if constexpr (AHALF) {
            #pragma unroll
            for (int i = 0; i < ALH; i++) {
                int idx = tid + i * THREADS;
                int r = idx >> 3, u = idx & 7;           // 8 uint4 per 128B row
                int row = m0 + r; if (row >= M) row = M - 1;
                regAp[i] = __ldg((const uint4*)(Ah + (size_t)row * K + k0) + u);
            }
        } else {
            #pragma unroll
            for (int i = 0; i < ALF; i++) {
                int idx = tid + i * THREADS;
                int r = idx >> 4, c4 = (idx & 15) << 2;
                int row = m0 + r; if (row >= M) row = M - 1;
                float4 v = __ldg((const float4*)(Af + (size_t)row * K + k0 + c4));
                regAh[i] = cvt_hi(v);
            }
        }
        #pragma unroll
        for (int i = 0; i < BL; i++) {
            int idx = tid + i * THREADS;
            int r = idx >> 4, c4 = (idx & 15) << 2;
            float4 v = __ldg((const float4*)(W + (size_t)r * K + k0 + c4));
            regBh[i] = cvt_hi(v);
            regBl[i] = cvt_lo(v, regBh[i]);
        }
    };

    auto stsChunk = [&](int b) {
        char* base = smem + b * BUF;
        char* aHi  = base;
        char* bHi  = base + ASZ;
        char* bLo  = bHi + BSZ;
        if constexpr (AHALF) {
            #pragma unroll
            for (int i = 0; i < ALH; i++) {
                int idx = tid + i * THREADS;
                int r = idx >> 3, u = idx & 7;
                *(uint4*)(aHi + sw128((uint32_t)(r * 128 + u * 16))) = regAp[i];
            }
        } else {
            #pragma unroll
            for (int i = 0; i < ALF; i++) {
                int idx = tid + i * THREADS;
                int r = idx >> 4, c4 = (idx & 15) << 2;
                *(uint2*)(aHi + sw128((uint32_t)(r * 128 + c4 * 2))) = regAh[i];
            }
        }
        #pragma unroll
        for (int i = 0; i < BL; i++) {
            int idx = tid + i * THREADS;
            int r = idx >> 4, c4 = (idx & 15) << 2;
            uint32_t off = sw128((uint32_t)(r * 128 + c4 * 2));
            *(uint2*)(bHi + off) = regBh[i];
            *(uint2*)(bLo + off) = regBl[i];
        }
    };

    auto compute = [&](int b) {
        const uint32_t sAhi = sb + b * BUF;
        const uint32_t sBhi = sAhi + ASZ;
        const uint32_t sBlo = sBhi + BSZ;
        #pragma unroll
        for (int kb = 0; kb < 4; kb++) {
            const int kboff = kb * 32;
            uint32_t aH[MT][4];
            #pragma unroll
            for (int mt = 0; mt < MT; mt++) {
                uint32_t rowb = (uint32_t)((wmBase + mt * 16 + arow) * 128);
                ldsm_x4(aH[mt], sAhi + sw128(rowb + kboff + acol));
            }
            uint32_t bH[NT][2], bLo[NT][2];
            #pragma unroll
            for (int nt = 0; nt < NT; nt += 2) {
                uint32_t rowb = (uint32_t)((wnBase + nt * 8 + brow) * 128);
                uint32_t t[4];
                ldsm_x4(t, sBhi + sw128(rowb + kboff + bcol));
                bH[nt][0] = t[0]; bH[nt][1] = t[1];
                bH[nt + 1][0] = t[2]; bH[nt + 1][1] = t[3];
                ldsm_x4(t, sBlo + sw128(rowb + kboff + bcol));
                bLo[nt][0] = t[0]; bLo[nt][1] = t[1];
                bLo[nt + 1][0] = t[2]; bLo[nt + 1][1] = t[3];
            }
            #pragma unroll
            for (int mt = 0; mt < MT; mt++)
                #pragma unroll
                for (int nt = 0; nt < NT; nt++) {
                    mma16816(acc[mt][nt], aH[mt], bH[nt]);
                    mma16816(acc[mt][nt], aH[mt], bLo[nt]);
                }
        }
    };

    loadChunk(0);
    stsChunk(0);
    __syncthreads();

    for (int c = 0; c < NCHUNK; c++) {
        if (c + 1 < NCHUNK) loadChunk(c + 1);
        compute(c & 1);
        if (c + 1 < NCHUNK) {
            __syncthreads();
            stsChunk((c + 1) & 1);
            __syncthreads();
        }
    }

    #pragma unroll
    for (int mt = 0; mt < MT; mt++) {
        int m = m0 + wmBase + mt * 16 + (l >> 2);
        #pragma unroll
        for (int nt = 0; nt < NT; nt++) {
            int nn = wnBase + nt * 8 + ((l & 3) << 1);
            if (m < M)
                *(__half2*)(C + (size_t)m * BN + nn) =
                    __floats2half2_rn(acc[mt][nt][0], acc[mt][nt][1]);
            if (m + 8 < M)
                *(__half2*)(C + (size_t)(m + 8) * BN + nn) =
                    __floats2half2_rn(acc[mt][nt][2], acc[mt][nt][3]);
        }
    }
}

// ---------------- SpMM (CSR, warp per row, fp16 gather, 2x unroll) ---------
// h fp16, accumulate fp32. OUTHALF: store fp16, else fp32.
template <int WIDTH, bool RELU, bool OUTHALF>
__global__ void spmm_kernel(const __half* __restrict__ h,
                            void* __restrict__ outv, int n) {
    int warp = (blockIdx.x * blockDim.x + threadIdx.x) >> 5;
    int lane = threadIdx.x & 31;
    if (warp >= n) return;
    int s = g_rowptr[warp];
    int e = g_rowptr[warp + 1];

    if (WIDTH == 128) {
        float4 acc = make_float4(0.f, 0.f, 0.f, 0.f);
        int i = s;
        for (; i + 2 <= e; i += 2) {
            int2 p0 = g_epack[i];
            int2 p1 = g_epack[i + 1];
            float v0 = __int_as_float(p0.y);
            float v1 = __int_as_float(p1.y);
            uint2 r0 = __ldg((const uint2*)(h + (size_t)p0.x * 128) + lane);
            uint2 r1 = __ldg((const uint2*)(h + (size_t)p1.x * 128) + lane);
            float2 a01 = __half22float2(*(__half2*)&r0.x);
            float2 a23 = __half22float2(*(__half2*)&r0.y);
            float2 b01 = __half22float2(*(__half2*)&r1.x);
            float2 b23 = __half22float2(*(__half2*)&r1.y);
            acc.x += v0 * a01.x; acc.y += v0 * a01.y;
            acc.z += v0 * a23.x; acc.w += v0 * a23.y;
            acc.x += v1 * b01.x; acc.y += v1 * b01.y;
            acc.z += v1 * b23.x; acc.w += v1 * b23.y;
        }
        if (i < e) {
            int2 p = g_epack[i];
            float v = __int_as_float(p.y);
            uint2 r0 = __ldg((const uint2*)(h + (size_t)p.x * 128) + lane);
            float2 a01 = __half22float2(*(__half2*)&r0.x);
            float2 a23 = __half22float2(*(__half2*)&r0.y);
            acc.x += v * a01.x; acc.y += v * a01.y;
            acc.z += v * a23.x; acc.w += v * a23.y;
        }
        if (RELU) {
            acc.x = fmaxf(acc.x, 0.f); acc.y = fmaxf(acc.y, 0.f);
            acc.z = fmaxf(acc.z, 0.f); acc.w = fmaxf(acc.w, 0.f);
        }
        if constexpr (OUTHALF) {
            __half2 o01 = __floats2half2_rn(acc.x, acc.y);
            __half2 o23 = __floats2half2_rn(acc.z, acc.w);
            ((uint2*)((__half*)outv + (size_t)warp * 128))[lane] =
                make_uint2(*(uint32_t*)&o01, *(uint32_t*)&o23);
        } else {
            ((float4*)((float*)outv + (size_t)warp * 128))[lane] = acc;
        }
    } else {  // WIDTH == 64
        float2 acc = make_float2(0.f, 0.f);
        int i = s;
        for (; i + 2 <= e; i += 2) {
            int2 p0 = g_epack[i];
            int2 p1 = g_epack[i + 1];
            float v0 = __int_as_float(p0.y);
            float v1 = __int_as_float(p1.y);
            uint32_t r0 = __ldg((const uint32_t*)(h + (size_t)p0.x * 64) + lane);
            uint32_t r1 = __ldg((const uint32_t*)(h + (size_t)p1.x * 64) + lane);
            float2 a = __half22float2(*(__half2*)&r0);
            float2 b = __half22float2(*(__half2*)&r1);
            acc.x += v0 * a.x; acc.y += v0 * a.y;
            acc.x += v1 * b.x; acc.y += v1 * b.y;
        }
        if (i < e) {
            int2 p = g_epack[i];
            float v = __int_as_float(p.y);
            uint32_t r0 = __ldg((const uint32_t*)(h + (size_t)p.x * 64) + lane);
            float2 a = __half22float2(*(__half2*)&r0);
            acc.x += v * a.x; acc.y += v * a.y;
        }
        if (RELU) { acc.x = fmaxf(acc.x, 0.f); acc.y = fmaxf(acc.y, 0.f); }
        ((float2*)((float*)outv + (size_t)warp * 64))[lane] = acc;
    }
}

// ---------------- Launcher ----------------
extern "C" void kernel_launch(void* const* d_in, const int* in_sizes, int n_in,
                              void* d_out, int out_size) {
    const float* x    = (const float*)d_in[0];
    const int*   rows = (const int*)  d_in[1];
    const int*   cols = (const int*)  d_in[2];
    const float* vals = (const float*)d_in[3];
    const float* W0   = (const float*)d_in[4];
    const float* W1   = (const float*)d_in[5];
    const float* W2   = (const float*)d_in[6];
    float* out = (float*)d_out;

    int n = in_sizes[0] / DIM_IN;   // 100000
    int E = in_sizes[1];            // 1600000
    int nb = (n + SCAN_BLK - 1) / SCAN_BLK;

    float* bufA; float* bufB;
    cudaGetSymbolAddress((void**)&bufA, g_bufA);
    cudaGetSymbolAddress((void**)&bufB, g_bufB);
    __half* bufAh = (__half*)bufA;
    __half* bufBh = (__half*)bufB;

    // smem per stage: ASZ 16K + 2*BSZ (BN=128: 32K -> 48K; BN=64: 16K -> 32K)
    const int smemG0 = 2 * 48 * 1024;
    const int smemG2 = 2 * 32 * 1024;
    cudaFuncSetAttribute(mma_gemm_kernel<128, 128, 2, 4, 512, false>,
                         cudaFuncAttributeMaxDynamicSharedMemorySize, smemG0);
    cudaFuncSetAttribute(mma_gemm_kernel<128, 128, 2, 4, 128, true>,
                         cudaFuncAttributeMaxDynamicSharedMemorySize, smemG0);
    cudaFuncSetAttribute(mma_gemm_kernel<128, 64, 4, 2, 128, true>,
                         cudaFuncAttributeMaxDynamicSharedMemorySize, smemG2);

    // ---- CSR build (multi-block scan) ----
    zero_counts_kernel<<<(n + 255) / 256, 256>>>(n);
    hist_kernel<<<(E + 255) / 256, 256>>>(rows, E);
    scan_blocks_kernel<<<nb, SCAN_BLK>>>(n);
    scan_partials_kernel<<<1, 128>>>(nb, n);
    scan_add_kernel<<<nb, SCAN_BLK>>>(n);
    scatter_kernel<<<(E + 255) / 256, 256>>>(rows, cols, vals, E);

    int gemmGrid = (n + 127) / 128;
    int spmmGrid = (n + 7) / 8;

    // layer 0: x(fp32) @ W0^T -> fp16; spmm fp16->fp16 + relu
    mma_gemm_kernel<128, 128, 2, 4, 512, false><<<gemmGrid, 256, smemG0>>>(x, W0, bufAh, n);
    spmm_kernel<128, true, true><<<spmmGrid, 256>>>(bufAh, bufBh, n);

    // layer 1: h(fp16) @ W1^T -> fp16; spmm fp16->fp16 + relu
    mma_gemm_kernel<128, 128, 2, 4, 128, true><<<gemmGrid, 256, smemG0>>>(bufBh, W1, bufAh, n);
    spmm_kernel<128, true, true><<<spmmGrid, 256>>>(bufAh, bufBh, n);

    // layer 2: h(fp16) @ W2^T -> fp16; spmm fp16->fp32 (no relu)
    mma_gemm_kernel<128, 64, 4, 2, 128, true><<<gemmGrid, 256, smemG2>>>(bufBh, W2, bufAh, n);
    spmm_kernel<64, false, false><<<spmmGrid, 256>>>(bufAh, out, n);
}